// round 1
// baseline (speedup 1.0000x reference)
#include <cuda_runtime.h>

typedef unsigned long long ull;

#define Bdim   256
#define Hdim   1024
#define G4     4096        // 4*H, packed as j = hcol*4 + gate (i,f,g,o)
#define Tsteps 128
#define DO     128

// ---------------- device scratch (allocation-free: __device__ globals) -----
__device__ float g_Wp0[(size_t)Hdim * G4];   // packed W_ih       [k][j]
__device__ float g_Wp [(size_t)Hdim * G4];   // packed W_ih+W_hh  [k][j]
__device__ float g_bp [G4];                  // packed b_ih+b_hh  [j]
__device__ float g_WoT[(size_t)Hdim * DO];   // W_out^T           [k][d]
__device__ float g_c  [(size_t)Bdim * Hdim]; // cell state
__device__ float g_seq[(size_t)Tsteps * Bdim * Hdim]; // h_t history

// ---------------- helpers ---------------------------------------------------
__device__ __forceinline__ ull pack2(float x) {
    ull r; unsigned u = __float_as_uint(x);
    asm("mov.b64 %0, {%1, %1};" : "=l"(r) : "r"(u));
    return r;
}
__device__ __forceinline__ void fma2(ull &d, ull a, ull b) {
    asm("fma.rn.f32x2 %0, %1, %2, %0;" : "+l"(d) : "l"(a), "l"(b));
}
__device__ __forceinline__ float lo32(ull v) { return __uint_as_float((unsigned)v); }
__device__ __forceinline__ float hi32(ull v) { return __uint_as_float((unsigned)(v >> 32)); }
__device__ __forceinline__ float sigf(float v)  { return 1.0f / (1.0f + __expf(-v)); }
__device__ __forceinline__ float tanhf_(float v){ return 2.0f / (1.0f + __expf(-2.0f * v)) - 1.0f; }

// ---------------- pack kernel ----------------------------------------------
__global__ void pack_kernel(const float* __restrict__ Wih, const float* __restrict__ Whh,
                            const float* __restrict__ bih, const float* __restrict__ bhh,
                            const float* __restrict__ Wout) {
    int idx = blockIdx.x * 256 + threadIdx.x;     // 0 .. Hdim*G4-1
    {
        int k = idx & (Hdim - 1);
        int j = idx >> 10;                        // 0..4095
        int hcol = j >> 2, g = j & 3;
        size_t src = (size_t)(g * Hdim + hcol) * Hdim + k;
        float wi = Wih[src];
        g_Wp0[(size_t)k * G4 + j] = wi;
        g_Wp [(size_t)k * G4 + j] = wi + Whh[src];
    }
    if (idx < G4) {
        int hcol = idx >> 2, g = idx & 3;
        g_bp[idx] = bih[g * Hdim + hcol] + bhh[g * Hdim + hcol];
    }
    if (idx < Hdim * DO) {
        int k = idx >> 7, d = idx & (DO - 1);
        g_WoT[idx] = Wout[(size_t)d * Hdim + k];
    }
}

// ---------------- fused LSTM step: gates GEMM + cell update -----------------
// gates[B=256, 4096] = inp[256,1024] @ Wp[1024,4096], epilogue applies LSTM cell.
// Tile 64 (batch rows) x 128 (gate cols = 32 hcols * 4 gates). 128 CTAs = 1 wave.
__global__ __launch_bounds__(256, 1) void lstm_step_kernel(const float* __restrict__ x, int t) {
    __shared__ float As[32][65];                        // [k][row], padded
    __shared__ __align__(16) float Bs[32][128];         // [k][j]

    const float* __restrict__ inp = (t == 0) ? x : (g_seq + (size_t)(t - 1) * Bdim * Hdim);
    const float* __restrict__ Wp  = (t == 0) ? g_Wp0 : g_Wp;
    float* __restrict__ hout = g_seq + (size_t)t * Bdim * Hdim;

    const int tid = threadIdx.x;
    const int tx = tid & 15, ty = tid >> 4;
    const int r0 = blockIdx.y * 64;
    const int j0 = blockIdx.x * 128;

    const int aK4 = tid & 7, aRow = tid >> 3;   // A loader: 8 float4 along k, 32 rows/pass
    const int bJ4 = tid & 31, bK  = tid >> 5;   // B loader: 32 float4 along j, 8 k/pass

    ull acc[4][4];
    #pragma unroll
    for (int i = 0; i < 4; i++)
        #pragma unroll
        for (int p = 0; p < 4; p++) acc[i][p] = 0ull;

    float4 aReg[2], bReg[4];
    #pragma unroll
    for (int p = 0; p < 2; p++)
        aReg[p] = *(const float4*)&inp[(size_t)(r0 + aRow + p * 32) * Hdim + aK4 * 4];
    #pragma unroll
    for (int p = 0; p < 4; p++)
        bReg[p] = *(const float4*)&Wp[(size_t)(bK + p * 8) * G4 + j0 + bJ4 * 4];

    for (int k0 = 0; k0 < Hdim; k0 += 32) {
        // stage registers -> smem
        #pragma unroll
        for (int p = 0; p < 2; p++) {
            int row = aRow + p * 32;
            As[aK4 * 4 + 0][row] = aReg[p].x;
            As[aK4 * 4 + 1][row] = aReg[p].y;
            As[aK4 * 4 + 2][row] = aReg[p].z;
            As[aK4 * 4 + 3][row] = aReg[p].w;
        }
        #pragma unroll
        for (int p = 0; p < 4; p++)
            *(float4*)&Bs[bK + p * 8][bJ4 * 4] = bReg[p];
        __syncthreads();

        // prefetch next tile (hidden under compute)
        int kn = k0 + 32;
        if (kn < Hdim) {
            #pragma unroll
            for (int p = 0; p < 2; p++)
                aReg[p] = *(const float4*)&inp[(size_t)(r0 + aRow + p * 32) * Hdim + kn + aK4 * 4];
            #pragma unroll
            for (int p = 0; p < 4; p++)
                bReg[p] = *(const float4*)&Wp[(size_t)(kn + bK + p * 8) * G4 + j0 + bJ4 * 4];
        }

        // FFMA2 inner loop: 16 packed FMA per thread per k (= 32 fp32 FMA)
        #pragma unroll
        for (int kk = 0; kk < 32; kk++) {
            ulonglong2 b01 = *(const ulonglong2*)&Bs[kk][tx * 8];
            ulonglong2 b23 = *(const ulonglong2*)&Bs[kk][tx * 8 + 4];
            #pragma unroll
            for (int i = 0; i < 4; i++) {
                ull Ar = pack2(As[kk][ty * 4 + i]);
                fma2(acc[i][0], Ar, b01.x);
                fma2(acc[i][1], Ar, b01.y);
                fma2(acc[i][2], Ar, b23.x);
                fma2(acc[i][3], Ar, b23.y);
            }
        }
        __syncthreads();
    }

    // ---- fused LSTM cell epilogue ----
    const bool first = (t == 0);
    float bias[8];
    #pragma unroll
    for (int c = 0; c < 8; c++) bias[c] = g_bp[j0 + tx * 8 + c];

    #pragma unroll
    for (int i = 0; i < 4; i++) {
        int brow = r0 + ty * 4 + i;
        #pragma unroll
        for (int m = 0; m < 2; m++) {
            float vi = lo32(acc[i][2 * m + 0]) + bias[4 * m + 0];
            float vf = hi32(acc[i][2 * m + 0]) + bias[4 * m + 1];
            float vg = lo32(acc[i][2 * m + 1]) + bias[4 * m + 2];
            float vo = hi32(acc[i][2 * m + 1]) + bias[4 * m + 3];
            int hc = (j0 >> 2) + tx * 2 + m;
            size_t idx = (size_t)brow * Hdim + hc;
            float c_old = first ? 0.0f : g_c[idx];
            float cn = sigf(vf) * c_old + sigf(vi) * tanhf_(vg);
            float hn = sigf(vo) * tanhf_(cn);
            g_c[idx]  = cn;
            hout[idx] = hn;
        }
    }
}

// ---------------- final projection: out[b,t,:] = h_t[b] @ W_out^T + b_out ---
// A = g_seq as [32768,1024] (m = t*256 + b), B = g_WoT [1024,128].
__global__ __launch_bounds__(256, 1) void proj_kernel(const float* __restrict__ bout,
                                                      float* __restrict__ out) {
    __shared__ float As[32][65];
    __shared__ __align__(16) float Bs[32][128];

    const int tid = threadIdx.x;
    const int tx = tid & 15, ty = tid >> 4;
    const int r0 = blockIdx.x * 64;

    const int aK4 = tid & 7, aRow = tid >> 3;
    const int bJ4 = tid & 31, bK  = tid >> 5;

    ull acc[4][4];
    #pragma unroll
    for (int i = 0; i < 4; i++)
        #pragma unroll
        for (int p = 0; p < 4; p++) acc[i][p] = 0ull;

    float4 aReg[2], bReg[4];
    #pragma unroll
    for (int p = 0; p < 2; p++)
        aReg[p] = *(const float4*)&g_seq[(size_t)(r0 + aRow + p * 32) * Hdim + aK4 * 4];
    #pragma unroll
    for (int p = 0; p < 4; p++)
        bReg[p] = *(const float4*)&g_WoT[(size_t)(bK + p * 8) * DO + bJ4 * 4];

    for (int k0 = 0; k0 < Hdim; k0 += 32) {
        #pragma unroll
        for (int p = 0; p < 2; p++) {
            int row = aRow + p * 32;
            As[aK4 * 4 + 0][row] = aReg[p].x;
            As[aK4 * 4 + 1][row] = aReg[p].y;
            As[aK4 * 4 + 2][row] = aReg[p].z;
            As[aK4 * 4 + 3][row] = aReg[p].w;
        }
        #pragma unroll
        for (int p = 0; p < 4; p++)
            *(float4*)&Bs[bK + p * 8][bJ4 * 4] = bReg[p];
        __syncthreads();

        int kn = k0 + 32;
        if (kn < Hdim) {
            #pragma unroll
            for (int p = 0; p < 2; p++)
                aReg[p] = *(const float4*)&g_seq[(size_t)(r0 + aRow + p * 32) * Hdim + kn + aK4 * 4];
            #pragma unroll
            for (int p = 0; p < 4; p++)
                bReg[p] = *(const float4*)&g_WoT[(size_t)(kn + bK + p * 8) * DO + bJ4 * 4];
        }

        #pragma unroll
        for (int kk = 0; kk < 32; kk++) {
            ulonglong2 b01 = *(const ulonglong2*)&Bs[kk][tx * 8];
            ulonglong2 b23 = *(const ulonglong2*)&Bs[kk][tx * 8 + 4];
            #pragma unroll
            for (int i = 0; i < 4; i++) {
                ull Ar = pack2(As[kk][ty * 4 + i]);
                fma2(acc[i][0], Ar, b01.x);
                fma2(acc[i][1], Ar, b01.y);
                fma2(acc[i][2], Ar, b23.x);
                fma2(acc[i][3], Ar, b23.y);
            }
        }
        __syncthreads();
    }

    float bias[8];
    #pragma unroll
    for (int c = 0; c < 8; c++) bias[c] = bout[tx * 8 + c];

    #pragma unroll
    for (int i = 0; i < 4; i++) {
        int m_ = r0 + ty * 4 + i;          // m = t*256 + b
        int tt = m_ >> 8, bb = m_ & 255;
        float* orow = out + ((size_t)bb * Tsteps + tt) * DO;
        #pragma unroll
        for (int p = 0; p < 4; p++) {
            float2 v;
            v.x = lo32(acc[i][p]) + bias[2 * p + 0];
            v.y = hi32(acc[i][p]) + bias[2 * p + 1];
            *(float2*)&orow[tx * 8 + 2 * p] = v;
        }
    }
}

// ---------------- launcher ---------------------------------------------------
extern "C" void kernel_launch(void* const* d_in, const int* in_sizes, int n_in,
                              void* d_out, int out_size) {
    const float* x    = (const float*)d_in[0];
    const float* Wih  = (const float*)d_in[1];
    const float* Whh  = (const float*)d_in[2];
    const float* bih  = (const float*)d_in[3];
    const float* bhh  = (const float*)d_in[4];
    const float* Wout = (const float*)d_in[5];
    const float* bout = (const float*)d_in[6];
    float* out = (float*)d_out;

    pack_kernel<<<(Hdim * G4) / 256, 256>>>(Wih, Whh, bih, bhh, Wout);

    for (int t = 0; t < Tsteps; t++)
        lstm_step_kernel<<<dim3(32, 4), 256>>>(x, t);

    proj_kernel<<<(Tsteps * Bdim) / 64, 256>>>(bout, out);
}

// round 3
// speedup vs baseline: 2.1836x; 2.1836x over previous
#include <cuda_runtime.h>
#include <cuda_bf16.h>
#include <cstdint>

typedef unsigned long long ull;

#define Bdim   256
#define Hdim   1024
#define G4     4096
#define Tsteps 128
#define DO     128
#define NCH    16                 // K chunks of 64
#define TILE_ELEMS (128 * 64)     // (128-row x 64-k) bf16 tile

// ---------------- device scratch ------------------------------------------
__device__ __nv_bfloat16 g_B0h[(size_t)G4 * Hdim], g_B0l[(size_t)G4 * Hdim]; // W_ih split, [nt][c][jl][kin]
__device__ __nv_bfloat16 g_Bch[(size_t)G4 * Hdim], g_Bcl[(size_t)G4 * Hdim]; // (W_ih+W_hh) split
__device__ __nv_bfloat16 g_xAh[(size_t)Bdim * Hdim], g_xAl[(size_t)Bdim * Hdim]; // x split, [rt][c][rl][kin]
__device__ __nv_bfloat16 g_hh[(size_t)Tsteps * Bdim * Hdim];  // h hi
__device__ __nv_bfloat16 g_hl[(size_t)Tsteps * Bdim * Hdim];  // h lo
__device__ float g_seq[(size_t)Tsteps * Bdim * Hdim];         // h fp32 [t][b][k]
__device__ float g_c[(size_t)Bdim * Hdim];                    // cell state [r][hc]
__device__ float g_bp[G4];                                    // bias, j = hcol*4+gate
__device__ float g_WoT[(size_t)Hdim * DO];

// ---------------- helpers ---------------------------------------------------
__device__ __forceinline__ uint32_t smem_u32(const void* p) {
    uint32_t a;
    asm("{ .reg .u64 t; cvta.to.shared.u64 t, %1; cvt.u32.u64 %0, t; }" : "=r"(a) : "l"(p));
    return a;
}
__device__ __forceinline__ float sigf(float v)   { return 1.0f / (1.0f + __expf(-v)); }
__device__ __forceinline__ float tanhf_(float v) { return 2.0f / (1.0f + __expf(-2.0f * v)) - 1.0f; }

__device__ __forceinline__ void cpasync16(uint32_t dst, const void* src) {
    asm volatile("cp.async.cg.shared.global [%0], [%1], 16;" :: "r"(dst), "l"(src) : "memory");
}
__device__ __forceinline__ void cp_commit() { asm volatile("cp.async.commit_group;" ::: "memory"); }

__device__ __forceinline__ void ldm_x4(uint32_t* r, uint32_t addr) {
    asm volatile("ldmatrix.sync.aligned.m8n8.x4.shared.b16 {%0,%1,%2,%3}, [%4];"
                 : "=r"(r[0]), "=r"(r[1]), "=r"(r[2]), "=r"(r[3]) : "r"(addr));
}
__device__ __forceinline__ void mma_bf16(float* d, const uint32_t* a, uint32_t b0, uint32_t b1) {
    asm volatile(
        "mma.sync.aligned.m16n8k16.row.col.f32.bf16.bf16.f32 "
        "{%0,%1,%2,%3}, {%4,%5,%6,%7}, {%8,%9}, {%0,%1,%2,%3};"
        : "+f"(d[0]), "+f"(d[1]), "+f"(d[2]), "+f"(d[3])
        : "r"(a[0]), "r"(a[1]), "r"(a[2]), "r"(a[3]), "r"(b0), "r"(b1));
}
// ldmatrix lane address into a swizzled [row][64k] bf16 tile (128B rows)
__device__ __forceinline__ uint32_t tile_addr(uint32_t base, int row0, int k0, int lane) {
    int g = lane >> 3;
    int r = row0 + (lane & 7) + ((g & 1) << 3);
    int kE = k0 + ((g >> 1) << 3);
    return base + r * 128 + ((kE * 2) ^ ((r & 7) << 4));
}

__device__ __forceinline__ ull pack2(float x) {
    ull r; unsigned u = __float_as_uint(x);
    asm("mov.b64 %0, {%1, %1};" : "=l"(r) : "r"(u));
    return r;
}
__device__ __forceinline__ void fma2(ull &d, ull a, ull b) {
    asm("fma.rn.f32x2 %0, %1, %2, %0;" : "+l"(d) : "l"(a), "l"(b));
}
__device__ __forceinline__ float lo32(ull v) { return __uint_as_float((unsigned)v); }
__device__ __forceinline__ float hi32(ull v) { return __uint_as_float((unsigned)(v >> 32)); }

// ---------------- pack kernel ----------------------------------------------
__global__ void pack_kernel(const float* __restrict__ Wih, const float* __restrict__ Whh,
                            const float* __restrict__ bih, const float* __restrict__ bhh,
                            const float* __restrict__ Wout, const float* __restrict__ x) {
    size_t idx = (size_t)blockIdx.x * 256 + threadIdx.x;   // 0 .. G4*Hdim-1
    {
        int j = (int)(idx >> 10), k = (int)(idx & 1023);
        int hcol = j >> 2, g = j & 3;
        size_t src = (size_t)(g * Hdim + hcol) * Hdim + k;
        float wi = Wih[src];
        float wc = wi + Whh[src];
        size_t dst = ((size_t)((j >> 7) * NCH + (k >> 6))) * TILE_ELEMS + (size_t)(j & 127) * 64 + (k & 63);
        __nv_bfloat16 h0 = __float2bfloat16(wi);
        g_B0h[dst] = h0;
        g_B0l[dst] = __float2bfloat16(wi - __bfloat162float(h0));
        __nv_bfloat16 hc_ = __float2bfloat16(wc);
        g_Bch[dst] = hc_;
        g_Bcl[dst] = __float2bfloat16(wc - __bfloat162float(hc_));
    }
    if (idx < (size_t)Bdim * Hdim) {
        int r = (int)(idx >> 10), k = (int)(idx & 1023);
        float v = x[idx];
        size_t dst = ((size_t)((r >> 7) * NCH + (k >> 6))) * TILE_ELEMS + (size_t)(r & 127) * 64 + (k & 63);
        __nv_bfloat16 h0 = __float2bfloat16(v);
        g_xAh[dst] = h0;
        g_xAl[dst] = __float2bfloat16(v - __bfloat162float(h0));
    }
    if (idx < G4) {
        int hcol = (int)idx >> 2, g = (int)idx & 3;
        g_bp[idx] = bih[g * Hdim + hcol] + bhh[g * Hdim + hcol];
    }
    if (idx < (size_t)Hdim * DO) {
        int k = (int)(idx >> 7), d = (int)(idx & (DO - 1));
        g_WoT[idx] = Wout[(size_t)d * Hdim + k];
    }
}

// ---------------- fused LSTM step (mma.sync bf16) ---------------------------
// grid (32 ntiles, 4 mtiles). CTA = 64 rows x 128 gate-cols. 8 warps of 32x32.
// smem per stage: Ah 8K | Al 8K | Bh 16K | Bl 16K = 48K; two stages = 96K.
#define STG_SZ 49152
#define OFF_AH 0
#define OFF_AL 8192
#define OFF_BH 16384
#define OFF_BL 32768
#define STEP_SMEM (2 * STG_SZ)

__global__ void __launch_bounds__(256, 1) lstm_step_kernel(int t) {
    extern __shared__ char smem[];
    const uint32_t sb = smem_u32(smem);
    const int tid = threadIdx.x;
    const int wid = tid >> 5, lane = tid & 31;
    const int nt = blockIdx.x, mt = blockIdx.y;
    const int rt = mt >> 1, rl0 = (mt & 1) * 64;

    const __nv_bfloat16 *Ah, *Al, *Bh, *Bl;
    if (t == 0) {
        Ah = g_xAh + (size_t)rt * NCH * TILE_ELEMS;
        Al = g_xAl + (size_t)rt * NCH * TILE_ELEMS;
        Bh = g_B0h + (size_t)nt * NCH * TILE_ELEMS;
        Bl = g_B0l + (size_t)nt * NCH * TILE_ELEMS;
    } else {
        size_t ab = ((size_t)(t - 1) * 2 + rt) * NCH * TILE_ELEMS;
        Ah = g_hh + ab;
        Al = g_hl + ab;
        Bh = g_Bch + (size_t)nt * NCH * TILE_ELEMS;
        Bl = g_Bcl + (size_t)nt * NCH * TILE_ELEMS;
    }

    // per-thread load slots
    const int arow = tid >> 3;                 // A: 2 passes of 32 rows? (64 rows, 512 x 16B)
    const int akb  = (tid & 7) * 16;
    const int brow = tid >> 3;                 // B: 4 passes of 32 rows (128 rows)
    const int bkb  = (tid & 7) * 16;

    auto issue = [&](int c, int s) {
        uint32_t stg = sb + s * STG_SZ;
        const char* pah = (const char*)(Ah + ((size_t)c * 128 + rl0) * 64);
        const char* pal = (const char*)(Al + ((size_t)c * 128 + rl0) * 64);
        const char* pbh = (const char*)(Bh + (size_t)c * 128 * 64);
        const char* pbl = (const char*)(Bl + (size_t)c * 128 * 64);
        #pragma unroll
        for (int p = 0; p < 2; p++) {
            int r = arow + p * 32;
            uint32_t sw = r * 128 + (akb ^ ((r & 7) << 4));
            cpasync16(stg + OFF_AH + sw, pah + r * 128 + akb);
            cpasync16(stg + OFF_AL + sw, pal + r * 128 + akb);
        }
        #pragma unroll
        for (int p = 0; p < 4; p++) {
            int r = brow + p * 32;
            uint32_t sw = r * 128 + (bkb ^ ((r & 7) << 4));
            cpasync16(stg + OFF_BH + sw, pbh + r * 128 + bkb);
            cpasync16(stg + OFF_BL + sw, pbl + r * 128 + bkb);
        }
        cp_commit();
    };

    const int wr = wid >> 2, wc = wid & 3;     // warp 32x32 tile
    const int mrow0 = wr * 32, n0 = wc * 32;

    float acc[2][4][4];
    #pragma unroll
    for (int mf = 0; mf < 2; mf++)
        #pragma unroll
        for (int nf = 0; nf < 4; nf++)
            #pragma unroll
            for (int q = 0; q < 4; q++) acc[mf][nf][q] = 0.0f;

    issue(0, 0);
    for (int c = 0; c < NCH; c++) {
        const int s = c & 1;
        if (c + 1 < NCH) {
            issue(c + 1, (c + 1) & 1);
            asm volatile("cp.async.wait_group 1;" ::: "memory");
        } else {
            asm volatile("cp.async.wait_group 0;" ::: "memory");
        }
        __syncthreads();

        uint32_t stg = sb + s * STG_SZ;
        #pragma unroll
        for (int kst = 0; kst < 4; kst++) {
            const int k0 = kst * 16;
            uint32_t fah[2][4], fal[2][4], fbh[2][4], fbl[2][4];
            #pragma unroll
            for (int mf = 0; mf < 2; mf++) {
                ldm_x4(fah[mf], tile_addr(stg + OFF_AH, mrow0 + mf * 16, k0, lane));
                ldm_x4(fal[mf], tile_addr(stg + OFF_AL, mrow0 + mf * 16, k0, lane));
            }
            #pragma unroll
            for (int hf = 0; hf < 2; hf++) {
                ldm_x4(fbh[hf], tile_addr(stg + OFF_BH, n0 + hf * 16, k0, lane));
                ldm_x4(fbl[hf], tile_addr(stg + OFF_BL, n0 + hf * 16, k0, lane));
            }
            #pragma unroll
            for (int mf = 0; mf < 2; mf++)
                #pragma unroll
                for (int nf = 0; nf < 4; nf++) {
                    const int hf = nf >> 1, lo = nf & 1;
                    mma_bf16(acc[mf][nf], fah[mf], fbh[hf][lo], fbh[hf][lo + 2]);
                    mma_bf16(acc[mf][nf], fah[mf], fbl[hf][lo], fbl[hf][lo + 2]);
                    mma_bf16(acc[mf][nf], fal[mf], fbh[hf][lo], fbh[hf][lo + 2]);
                }
        }
        __syncthreads();
    }

    // ---- fused LSTM cell epilogue ----
    const int quad = lane >> 2, qp = lane & 3;
    const bool oddl = (lane & 1) != 0;
    const bool first = (t == 0);
    const int mtb = mt * 64;

    #pragma unroll
    for (int mf = 0; mf < 2; mf++)
        #pragma unroll
        for (int nf = 0; nf < 4; nf++) {
            float* a = acc[mf][nf];
            int jb = nt * 128 + wc * 32 + nf * 8 + 2 * qp;
            float be = g_bp[jb], bo = g_bp[jb + 1];
            a[0] += be; a[1] += bo; a[2] += be; a[3] += bo;

            float p0 = __shfl_xor_sync(0xffffffffu, a[0], 1);
            float p1 = __shfl_xor_sync(0xffffffffu, a[1], 1);
            float p2 = __shfl_xor_sync(0xffffffffu, a[2], 1);
            float p3 = __shfl_xor_sync(0xffffffffu, a[3], 1);

            float vi = oddl ? p2 : a[0];
            float vf = oddl ? p3 : a[1];
            float vg = oddl ? a[2] : p0;
            float vo = oddl ? a[3] : p1;

            int row_g = mtb + wr * 32 + mf * 16 + quad + (oddl ? 8 : 0);
            int hc    = nt * 32 + wc * 8 + nf * 2 + (qp >> 1);

            size_t cidx = (size_t)row_g * Hdim + hc;
            float cold = first ? 0.0f : g_c[cidx];
            float cn = sigf(vf) * cold + sigf(vi) * tanhf_(vg);
            float hn = sigf(vo) * tanhf_(cn);
            g_c[cidx] = cn;

            g_seq[((size_t)t * Bdim + row_g) * Hdim + hc] = hn;

            __nv_bfloat16 h0 = __float2bfloat16(hn);
            __nv_bfloat16 h1 = __float2bfloat16(hn - __bfloat162float(h0));
            int rt2 = row_g >> 7, rl = row_g & 127;
            size_t hb = ((((size_t)t * 2 + rt2) * NCH + (hc >> 6)) * 128 + rl) * 64 + (hc & 63);
            g_hh[hb] = h0;
            g_hl[hb] = h1;
        }
}

// ---------------- final projection (fp32 FFMA2) ------------------------------
__global__ void __launch_bounds__(256, 1) proj_kernel(const float* __restrict__ bout,
                                                      float* __restrict__ out) {
    __shared__ float As[32][65];
    __shared__ __align__(16) float Bs[32][128];

    const int tid = threadIdx.x;
    const int tx = tid & 15, ty = tid >> 4;
    const int r0 = blockIdx.x * 64;

    const int aK4 = tid & 7, aRow = tid >> 3;
    const int bJ4 = tid & 31, bK  = tid >> 5;

    ull acc[4][4];
    #pragma unroll
    for (int i = 0; i < 4; i++)
        #pragma unroll
        for (int p = 0; p < 4; p++) acc[i][p] = 0ull;

    float4 aReg[2], bReg[4];
    #pragma unroll
    for (int p = 0; p < 2; p++)
        aReg[p] = *(const float4*)&g_seq[(size_t)(r0 + aRow + p * 32) * Hdim + aK4 * 4];
    #pragma unroll
    for (int p = 0; p < 4; p++)
        bReg[p] = *(const float4*)&g_WoT[(size_t)(bK + p * 8) * DO + bJ4 * 4];

    for (int k0 = 0; k0 < Hdim; k0 += 32) {
        #pragma unroll
        for (int p = 0; p < 2; p++) {
            int row = aRow + p * 32;
            As[aK4 * 4 + 0][row] = aReg[p].x;
            As[aK4 * 4 + 1][row] = aReg[p].y;
            As[aK4 * 4 + 2][row] = aReg[p].z;
            As[aK4 * 4 + 3][row] = aReg[p].w;
        }
        #pragma unroll
        for (int p = 0; p < 4; p++)
            *(float4*)&Bs[bK + p * 8][bJ4 * 4] = bReg[p];
        __syncthreads();

        int kn = k0 + 32;
        if (kn < Hdim) {
            #pragma unroll
            for (int p = 0; p < 2; p++)
                aReg[p] = *(const float4*)&g_seq[(size_t)(r0 + aRow + p * 32) * Hdim + kn + aK4 * 4];
            #pragma unroll
            for (int p = 0; p < 4; p++)
                bReg[p] = *(const float4*)&g_WoT[(size_t)(kn + bK + p * 8) * DO + bJ4 * 4];
        }

        #pragma unroll
        for (int kk = 0; kk < 32; kk++) {
            ulonglong2 b01 = *(const ulonglong2*)&Bs[kk][tx * 8];
            ulonglong2 b23 = *(const ulonglong2*)&Bs[kk][tx * 8 + 4];
            #pragma unroll
            for (int i = 0; i < 4; i++) {
                ull Ar = pack2(As[kk][ty * 4 + i]);
                fma2(acc[i][0], Ar, b01.x);
                fma2(acc[i][1], Ar, b01.y);
                fma2(acc[i][2], Ar, b23.x);
                fma2(acc[i][3], Ar, b23.y);
            }
        }
        __syncthreads();
    }

    float bias[8];
    #pragma unroll
    for (int c = 0; c < 8; c++) bias[c] = bout[tx * 8 + c];

    #pragma unroll
    for (int i = 0; i < 4; i++) {
        int m_ = r0 + ty * 4 + i;          // m = t*256 + b
        int tt = m_ >> 8, bb = m_ & 255;
        float* orow = out + ((size_t)bb * Tsteps + tt) * DO;
        #pragma unroll
        for (int p = 0; p < 4; p++) {
            float2 v;
            v.x = lo32(acc[i][p]) + bias[2 * p + 0];
            v.y = hi32(acc[i][p]) + bias[2 * p + 1];
            *(float2*)&orow[tx * 8 + 2 * p] = v;
        }
    }
}

// ---------------- launcher ---------------------------------------------------
extern "C" void kernel_launch(void* const* d_in, const int* in_sizes, int n_in,
                              void* d_out, int out_size) {
    const float* x    = (const float*)d_in[0];
    const float* Wih  = (const float*)d_in[1];
    const float* Whh  = (const float*)d_in[2];
    const float* bih  = (const float*)d_in[3];
    const float* bhh  = (const float*)d_in[4];
    const float* Wout = (const float*)d_in[5];
    const float* bout = (const float*)d_in[6];
    float* out = (float*)d_out;

    static bool attr_set = false;
    if (!attr_set) {
        cudaFuncSetAttribute(lstm_step_kernel, cudaFuncAttributeMaxDynamicSharedMemorySize, STEP_SMEM);
        attr_set = true;
    }

    pack_kernel<<<(G4 * Hdim) / 256, 256>>>(Wih, Whh, bih, bhh, Wout, x);

    for (int t = 0; t < Tsteps; t++)
        lstm_step_kernel<<<dim3(32, 4), 256, STEP_SMEM>>>(t);

    proj_kernel<<<(Tsteps * Bdim) / 64, 256>>>(bout, out);
}

// round 4
// speedup vs baseline: 2.4997x; 1.1447x over previous
#include <cuda_runtime.h>
#include <cuda_fp16.h>
#include <cstdint>

typedef unsigned long long ull;

#define Bdim   256
#define Hdim   1024
#define G4     4096
#define Tsteps 128
#define DO     128
#define NCH    16                 // K chunks of 64
#define TILE_ELEMS (128 * 64)     // (128-row x 64-k) half tile

// ---------------- device scratch ------------------------------------------
__device__ __half g_B0h[(size_t)G4 * Hdim], g_B0l[(size_t)G4 * Hdim]; // W_ih fp16 hi/lo, [nt][c][jl][kin]
__device__ __half g_Bch[(size_t)G4 * Hdim], g_Bcl[(size_t)G4 * Hdim]; // (W_ih+W_hh) fp16 hi/lo
__device__ __half g_xA[(size_t)Bdim * Hdim];                          // x fp16, [rt][c][rl][kin]
__device__ __half g_hf[(size_t)Tsteps * Bdim * Hdim];                 // h fp16, tiled
__device__ float g_seq[(size_t)Tsteps * Bdim * Hdim];                 // h fp32 [t][b][k]
__device__ float g_c[(size_t)Bdim * Hdim];                            // cell state [r][hc]
__device__ float g_bp[G4];                                            // bias, j = hcol*4+gate
__device__ float g_WoT[(size_t)Hdim * DO];

// ---------------- helpers ---------------------------------------------------
__device__ __forceinline__ uint32_t smem_u32(const void* p) {
    uint32_t a;
    asm("{ .reg .u64 t; cvta.to.shared.u64 t, %1; cvt.u32.u64 %0, t; }" : "=r"(a) : "l"(p));
    return a;
}
__device__ __forceinline__ float sigf(float v)   { return 1.0f / (1.0f + __expf(-v)); }
__device__ __forceinline__ float tanhf_(float v) { return 2.0f / (1.0f + __expf(-2.0f * v)) - 1.0f; }

__device__ __forceinline__ void cpasync16(uint32_t dst, const void* src) {
    asm volatile("cp.async.cg.shared.global [%0], [%1], 16;" :: "r"(dst), "l"(src) : "memory");
}
__device__ __forceinline__ void cp_commit() { asm volatile("cp.async.commit_group;" ::: "memory"); }

__device__ __forceinline__ void ldm_x4(uint32_t* r, uint32_t addr) {
    asm volatile("ldmatrix.sync.aligned.m8n8.x4.shared.b16 {%0,%1,%2,%3}, [%4];"
                 : "=r"(r[0]), "=r"(r[1]), "=r"(r[2]), "=r"(r[3]) : "r"(addr));
}
__device__ __forceinline__ void mma_f16(float* d, const uint32_t* a, uint32_t b0, uint32_t b1) {
    asm volatile(
        "mma.sync.aligned.m16n8k16.row.col.f32.f16.f16.f32 "
        "{%0,%1,%2,%3}, {%4,%5,%6,%7}, {%8,%9}, {%0,%1,%2,%3};"
        : "+f"(d[0]), "+f"(d[1]), "+f"(d[2]), "+f"(d[3])
        : "r"(a[0]), "r"(a[1]), "r"(a[2]), "r"(a[3]), "r"(b0), "r"(b1));
}
// ldmatrix lane address into a swizzled [row][64k] half tile (128B rows)
__device__ __forceinline__ uint32_t tile_addr(uint32_t base, int row0, int k0, int lane) {
    int g = lane >> 3;
    int r = row0 + (lane & 7) + ((g & 1) << 3);
    int kE = k0 + ((g >> 1) << 3);
    return base + r * 128 + ((kE * 2) ^ ((r & 7) << 4));
}

__device__ __forceinline__ ull pack2(float x) {
    ull r; unsigned u = __float_as_uint(x);
    asm("mov.b64 %0, {%1, %1};" : "=l"(r) : "r"(u));
    return r;
}
__device__ __forceinline__ void fma2(ull &d, ull a, ull b) {
    asm("fma.rn.f32x2 %0, %1, %2, %0;" : "+l"(d) : "l"(a), "l"(b));
}
__device__ __forceinline__ float lo32(ull v) { return __uint_as_float((unsigned)v); }
__device__ __forceinline__ float hi32(ull v) { return __uint_as_float((unsigned)(v >> 32)); }

// ---------------- pack kernel ----------------------------------------------
__global__ void pack_kernel(const float* __restrict__ Wih, const float* __restrict__ Whh,
                            const float* __restrict__ bih, const float* __restrict__ bhh,
                            const float* __restrict__ Wout, const float* __restrict__ x) {
    size_t idx = (size_t)blockIdx.x * 256 + threadIdx.x;   // 0 .. G4*Hdim-1
    {
        int j = (int)(idx >> 10), k = (int)(idx & 1023);
        int hcol = j >> 2, g = j & 3;
        size_t src = (size_t)(g * Hdim + hcol) * Hdim + k;
        float wi = Wih[src];
        float wc = wi + Whh[src];
        size_t dst = ((size_t)((j >> 7) * NCH + (k >> 6))) * TILE_ELEMS + (size_t)(j & 127) * 64 + (k & 63);
        __half h0 = __float2half_rn(wi);
        g_B0h[dst] = h0;
        g_B0l[dst] = __float2half_rn(wi - __half2float(h0));
        __half hc_ = __float2half_rn(wc);
        g_Bch[dst] = hc_;
        g_Bcl[dst] = __float2half_rn(wc - __half2float(hc_));
    }
    if (idx < (size_t)Bdim * Hdim) {
        int r = (int)(idx >> 10), k = (int)(idx & 1023);
        size_t dst = ((size_t)((r >> 7) * NCH + (k >> 6))) * TILE_ELEMS + (size_t)(r & 127) * 64 + (k & 63);
        g_xA[dst] = __float2half_rn(x[idx]);
    }
    if (idx < G4) {
        int hcol = (int)idx >> 2, g = (int)idx & 3;
        g_bp[idx] = bih[g * Hdim + hcol] + bhh[g * Hdim + hcol];
    }
    if (idx < (size_t)Hdim * DO) {
        int k = (int)(idx >> 7), d = (int)(idx & (DO - 1));
        g_WoT[idx] = Wout[(size_t)d * Hdim + k];
    }
}

// ---------------- fused LSTM step (mma.sync fp16, 2-pass weight split) ------
// grid (32 ntiles, 4 mtiles). CTA = 64 rows x 128 gate-cols. 8 warps of 32x32.
// stage: A 8K | Bh 16K | Bl 16K = 40K; 3 stages = 120K.
#define STG_SZ 40960
#define OFF_A  0
#define OFF_BH 8192
#define OFF_BL 24576
#define NSTG   3
#define STEP_SMEM (NSTG * STG_SZ)

__global__ void __launch_bounds__(256, 1) lstm_step_kernel(int t) {
    extern __shared__ char smem[];
    const uint32_t sb = smem_u32(smem);
    const int tid = threadIdx.x;
    const int wid = tid >> 5, lane = tid & 31;
    const int nt = blockIdx.x, mt = blockIdx.y;
    const int rt = mt >> 1, rl0 = (mt & 1) * 64;

    const __half *Aa, *Bh, *Bl;
    if (t == 0) {
        Aa = g_xA + (size_t)rt * NCH * TILE_ELEMS;
        Bh = g_B0h + (size_t)nt * NCH * TILE_ELEMS;
        Bl = g_B0l + (size_t)nt * NCH * TILE_ELEMS;
    } else {
        Aa = g_hf + ((size_t)(t - 1) * 2 + rt) * NCH * TILE_ELEMS;
        Bh = g_Bch + (size_t)nt * NCH * TILE_ELEMS;
        Bl = g_Bcl + (size_t)nt * NCH * TILE_ELEMS;
    }

    const int ldrow = tid >> 3;            // 0..31
    const int ldcol = (tid & 7) * 16;      // byte col in 128B row

    auto issue = [&](int c) {
        if (c < NCH) {
            uint32_t stg = sb + (c % NSTG) * STG_SZ;
            const char* pa  = (const char*)(Aa + ((size_t)c * 128 + rl0) * 64);
            const char* pbh = (const char*)(Bh + (size_t)c * 128 * 64);
            const char* pbl = (const char*)(Bl + (size_t)c * 128 * 64);
            #pragma unroll
            for (int p = 0; p < 2; p++) {
                int r = ldrow + p * 32;
                uint32_t sw = r * 128 + (ldcol ^ ((r & 7) << 4));
                cpasync16(stg + OFF_A + sw, pa + r * 128 + ldcol);
            }
            #pragma unroll
            for (int p = 0; p < 4; p++) {
                int r = ldrow + p * 32;
                uint32_t sw = r * 128 + (ldcol ^ ((r & 7) << 4));
                cpasync16(stg + OFF_BH + sw, pbh + r * 128 + ldcol);
                cpasync16(stg + OFF_BL + sw, pbl + r * 128 + ldcol);
            }
        }
        cp_commit();
    };

    const int wr = wid >> 2, wc = wid & 3;     // warp 32x32 tile
    const int mrow0 = wr * 32, n0 = wc * 32;

    float acc[2][4][4];
    #pragma unroll
    for (int mf = 0; mf < 2; mf++)
        #pragma unroll
        for (int nf = 0; nf < 4; nf++)
            #pragma unroll
            for (int q = 0; q < 4; q++) acc[mf][nf][q] = 0.0f;

    issue(0); issue(1);

    for (int c = 0; c < NCH; c++) {
        asm volatile("cp.async.wait_group 1;" ::: "memory");
        __syncthreads();

        uint32_t stg = sb + (c % NSTG) * STG_SZ;

        // fragment double-buffer over kst
        uint32_t fa[2][2][4], fbh[2][2][4], fbl[2][2][4];
        #pragma unroll
        for (int mf = 0; mf < 2; mf++)
            ldm_x4(fa[0][mf], tile_addr(stg + OFF_A, mrow0 + mf * 16, 0, lane));
        #pragma unroll
        for (int hf = 0; hf < 2; hf++) {
            ldm_x4(fbh[0][hf], tile_addr(stg + OFF_BH, n0 + hf * 16, 0, lane));
            ldm_x4(fbl[0][hf], tile_addr(stg + OFF_BL, n0 + hf * 16, 0, lane));
        }

        #pragma unroll
        for (int kst = 0; kst < 4; kst++) {
            const int cur = kst & 1, nxt = cur ^ 1;
            if (kst < 3) {
                const int k0 = (kst + 1) * 16;
                #pragma unroll
                for (int mf = 0; mf < 2; mf++)
                    ldm_x4(fa[nxt][mf], tile_addr(stg + OFF_A, mrow0 + mf * 16, k0, lane));
                #pragma unroll
                for (int hf = 0; hf < 2; hf++) {
                    ldm_x4(fbh[nxt][hf], tile_addr(stg + OFF_BH, n0 + hf * 16, k0, lane));
                    ldm_x4(fbl[nxt][hf], tile_addr(stg + OFF_BL, n0 + hf * 16, k0, lane));
                }
            }
            #pragma unroll
            for (int mf = 0; mf < 2; mf++)
                #pragma unroll
                for (int nf = 0; nf < 4; nf++) {
                    const int hf = nf >> 1, lo = nf & 1;
                    mma_f16(acc[mf][nf], fa[cur][mf], fbh[cur][hf][lo], fbh[cur][hf][lo + 2]);
                    mma_f16(acc[mf][nf], fa[cur][mf], fbl[cur][hf][lo], fbl[cur][hf][lo + 2]);
                }
        }
        issue(c + 2);
    }

    // ---- fused LSTM cell epilogue ----
    const int quad = lane >> 2, qp = lane & 3;
    const bool oddl = (lane & 1) != 0;
    const bool first = (t == 0);
    const int mtb = mt * 64;

    #pragma unroll
    for (int mf = 0; mf < 2; mf++)
        #pragma unroll
        for (int nf = 0; nf < 4; nf++) {
            float* a = acc[mf][nf];
            int jb = nt * 128 + wc * 32 + nf * 8 + 2 * qp;
            float be = g_bp[jb], bo = g_bp[jb + 1];
            a[0] += be; a[1] += bo; a[2] += be; a[3] += bo;

            float p0 = __shfl_xor_sync(0xffffffffu, a[0], 1);
            float p1 = __shfl_xor_sync(0xffffffffu, a[1], 1);
            float p2 = __shfl_xor_sync(0xffffffffu, a[2], 1);
            float p3 = __shfl_xor_sync(0xffffffffu, a[3], 1);

            float vi = oddl ? p2 : a[0];
            float vf = oddl ? p3 : a[1];
            float vg = oddl ? a[2] : p0;
            float vo = oddl ? a[3] : p1;

            int row_g = mtb + wr * 32 + mf * 16 + quad + (oddl ? 8 : 0);
            int hc    = nt * 32 + wc * 8 + nf * 2 + (qp >> 1);

            size_t cidx = (size_t)row_g * Hdim + hc;
            float cold = first ? 0.0f : g_c[cidx];
            float cn = sigf(vf) * cold + sigf(vi) * tanhf_(vg);
            float hn = sigf(vo) * tanhf_(cn);
            g_c[cidx] = cn;

            g_seq[((size_t)t * Bdim + row_g) * Hdim + hc] = hn;

            int rt2 = row_g >> 7, rl = row_g & 127;
            size_t hb = ((((size_t)t * 2 + rt2) * NCH + (hc >> 6)) * 128 + rl) * 64 + (hc & 63);
            g_hf[hb] = __float2half_rn(hn);
        }
}

// ---------------- final projection (fp32 FFMA2) ------------------------------
__global__ void __launch_bounds__(256, 1) proj_kernel(const float* __restrict__ bout,
                                                      float* __restrict__ out) {
    __shared__ float As[32][65];
    __shared__ __align__(16) float Bs[32][128];

    const int tid = threadIdx.x;
    const int tx = tid & 15, ty = tid >> 4;
    const int r0 = blockIdx.x * 64;

    const int aK4 = tid & 7, aRow = tid >> 3;
    const int bJ4 = tid & 31, bK  = tid >> 5;

    ull acc[4][4];
    #pragma unroll
    for (int i = 0; i < 4; i++)
        #pragma unroll
        for (int p = 0; p < 4; p++) acc[i][p] = 0ull;

    float4 aReg[2], bReg[4];
    #pragma unroll
    for (int p = 0; p < 2; p++)
        aReg[p] = *(const float4*)&g_seq[(size_t)(r0 + aRow + p * 32) * Hdim + aK4 * 4];
    #pragma unroll
    for (int p = 0; p < 4; p++)
        bReg[p] = *(const float4*)&g_WoT[(size_t)(bK + p * 8) * DO + bJ4 * 4];

    for (int k0 = 0; k0 < Hdim; k0 += 32) {
        #pragma unroll
        for (int p = 0; p < 2; p++) {
            int row = aRow + p * 32;
            As[aK4 * 4 + 0][row] = aReg[p].x;
            As[aK4 * 4 + 1][row] = aReg[p].y;
            As[aK4 * 4 + 2][row] = aReg[p].z;
            As[aK4 * 4 + 3][row] = aReg[p].w;
        }
        #pragma unroll
        for (int p = 0; p < 4; p++)
            *(float4*)&Bs[bK + p * 8][bJ4 * 4] = bReg[p];
        __syncthreads();

        int kn = k0 + 32;
        if (kn < Hdim) {
            #pragma unroll
            for (int p = 0; p < 2; p++)
                aReg[p] = *(const float4*)&g_seq[(size_t)(r0 + aRow + p * 32) * Hdim + kn + aK4 * 4];
            #pragma unroll
            for (int p = 0; p < 4; p++)
                bReg[p] = *(const float4*)&g_WoT[(size_t)(kn + bK + p * 8) * DO + bJ4 * 4];
        }

        #pragma unroll
        for (int kk = 0; kk < 32; kk++) {
            ulonglong2 b01 = *(const ulonglong2*)&Bs[kk][tx * 8];
            ulonglong2 b23 = *(const ulonglong2*)&Bs[kk][tx * 8 + 4];
            #pragma unroll
            for (int i = 0; i < 4; i++) {
                ull Ar = pack2(As[kk][ty * 4 + i]);
                fma2(acc[i][0], Ar, b01.x);
                fma2(acc[i][1], Ar, b01.y);
                fma2(acc[i][2], Ar, b23.x);
                fma2(acc[i][3], Ar, b23.y);
            }
        }
        __syncthreads();
    }

    float bias[8];
    #pragma unroll
    for (int c = 0; c < 8; c++) bias[c] = bout[tx * 8 + c];

    #pragma unroll
    for (int i = 0; i < 4; i++) {
        int m_ = r0 + ty * 4 + i;          // m = t*256 + b
        int tt = m_ >> 8, bb = m_ & 255;
        float* orow = out + ((size_t)bb * Tsteps + tt) * DO;
        #pragma unroll
        for (int p = 0; p < 4; p++) {
            float2 v;
            v.x = lo32(acc[i][p]) + bias[2 * p + 0];
            v.y = hi32(acc[i][p]) + bias[2 * p + 1];
            *(float2*)&orow[tx * 8 + 2 * p] = v;
        }
    }
}

// ---------------- launcher ---------------------------------------------------
extern "C" void kernel_launch(void* const* d_in, const int* in_sizes, int n_in,
                              void* d_out, int out_size) {
    const float* x    = (const float*)d_in[0];
    const float* Wih  = (const float*)d_in[1];
    const float* Whh  = (const float*)d_in[2];
    const float* bih  = (const float*)d_in[3];
    const float* bhh  = (const float*)d_in[4];
    const float* Wout = (const float*)d_in[5];
    const float* bout = (const float*)d_in[6];
    float* out = (float*)d_out;

    cudaFuncSetAttribute(lstm_step_kernel, cudaFuncAttributeMaxDynamicSharedMemorySize, STEP_SMEM);

    pack_kernel<<<(G4 * Hdim) / 256, 256>>>(Wih, Whh, bih, bhh, Wout, x);

    for (int t = 0; t < Tsteps; t++)
        lstm_step_kernel<<<dim3(32, 4), 256, STEP_SMEM>>>(t);

    proj_kernel<<<(Tsteps * Bdim) / 64, 256>>>(bout, out);
}

// round 5
// speedup vs baseline: 2.5955x; 1.0383x over previous
#include <cuda_runtime.h>
#include <cuda_fp16.h>
#include <cstdint>

typedef unsigned long long ull;

#define Bdim   256
#define Hdim   1024
#define G4     4096
#define Tsteps 128
#define DO     128
#define NCH    16                 // K chunks of 64
#define TILE_ELEMS (128 * 64)     // (128-row x 64-k) half tile

// ---------------- device scratch ------------------------------------------
__device__ __half g_B0h[(size_t)G4 * Hdim], g_B0l[(size_t)G4 * Hdim]; // W_ih fp16 hi/lo, [pt][c][jl][kin]
__device__ __half g_Bch[(size_t)G4 * Hdim], g_Bcl[(size_t)G4 * Hdim]; // (W_ih+W_hh) fp16 hi/lo
__device__ __half g_xA[(size_t)Bdim * Hdim];                          // x fp16, [rt][c][rl][kin]
__device__ __half g_hf[(size_t)Tsteps * Bdim * Hdim];                 // h fp16, tiled
__device__ float g_seq[(size_t)Tsteps * Bdim * Hdim];                 // h fp32 [t][b][k]
__device__ float g_c[(size_t)Bdim * Hdim];                            // cell state [r][hc]
__device__ float g_bp[G4];                                            // bias, j = hcol*4+gate
__device__ float g_WoT[(size_t)Hdim * DO];
__device__ unsigned g_cnt = 0, g_gen = 0;                             // grid barrier state

// ---------------- helpers ---------------------------------------------------
__device__ __forceinline__ uint32_t smem_u32(const void* p) {
    uint32_t a;
    asm("{ .reg .u64 t; cvta.to.shared.u64 t, %1; cvt.u32.u64 %0, t; }" : "=r"(a) : "l"(p));
    return a;
}
__device__ __forceinline__ float sigf(float v)   { return 1.0f / (1.0f + __expf(-v)); }
__device__ __forceinline__ float tanhf_(float v) { return 2.0f / (1.0f + __expf(-2.0f * v)) - 1.0f; }

__device__ __forceinline__ void cpasync16(uint32_t dst, const void* src) {
    asm volatile("cp.async.cg.shared.global [%0], [%1], 16;" :: "r"(dst), "l"(src) : "memory");
}
__device__ __forceinline__ void cp_commit() { asm volatile("cp.async.commit_group;" ::: "memory"); }

__device__ __forceinline__ void ldm_x4(uint32_t* r, uint32_t addr) {
    asm volatile("ldmatrix.sync.aligned.m8n8.x4.shared.b16 {%0,%1,%2,%3}, [%4];"
                 : "=r"(r[0]), "=r"(r[1]), "=r"(r[2]), "=r"(r[3]) : "r"(addr));
}
__device__ __forceinline__ void mma_f16(float* d, const uint32_t* a, uint32_t b0, uint32_t b1) {
    asm volatile(
        "mma.sync.aligned.m16n8k16.row.col.f32.f16.f16.f32 "
        "{%0,%1,%2,%3}, {%4,%5,%6,%7}, {%8,%9}, {%0,%1,%2,%3};"
        : "+f"(d[0]), "+f"(d[1]), "+f"(d[2]), "+f"(d[3])
        : "r"(a[0]), "r"(a[1]), "r"(a[2]), "r"(a[3]), "r"(b0), "r"(b1));
}
__device__ __forceinline__ uint32_t tile_addr(uint32_t base, int row0, int k0, int lane) {
    int g = lane >> 3;
    int r = row0 + (lane & 7) + ((g & 1) << 3);
    int kE = k0 + ((g >> 1) << 3);
    return base + r * 128 + ((kE * 2) ^ ((r & 7) << 4));
}

// software grid barrier (128 co-resident CTAs)
__device__ __forceinline__ void grid_bar() {
    __syncthreads();
    if (threadIdx.x == 0) {
        __threadfence();                               // publish h writes
        unsigned gen = atomicAdd(&g_gen, 0u);          // read gen BEFORE arriving
        if (atomicAdd(&g_cnt, 1u) == 127u) {
            atomicExch(&g_cnt, 0u);
            __threadfence();
            atomicAdd(&g_gen, 1u);                     // release
        } else {
            while (atomicAdd(&g_gen, 0u) == gen) __nanosleep(64);
        }
    }
    __syncthreads();
}

__device__ __forceinline__ ull pack2(float x) {
    ull r; unsigned u = __float_as_uint(x);
    asm("mov.b64 %0, {%1, %1};" : "=l"(r) : "r"(u));
    return r;
}
__device__ __forceinline__ void fma2(ull &d, ull a, ull b) {
    asm("fma.rn.f32x2 %0, %1, %2, %0;" : "+l"(d) : "l"(a), "l"(b));
}
__device__ __forceinline__ float lo32(ull v) { return __uint_as_float((unsigned)v); }
__device__ __forceinline__ float hi32(ull v) { return __uint_as_float((unsigned)(v >> 32)); }

// ---------------- pack kernel ----------------------------------------------
__global__ void pack_kernel(const float* __restrict__ Wih, const float* __restrict__ Whh,
                            const float* __restrict__ bih, const float* __restrict__ bhh,
                            const float* __restrict__ Wout, const float* __restrict__ x) {
    size_t idx = (size_t)blockIdx.x * 256 + threadIdx.x;
    {
        int j = (int)(idx >> 10), k = (int)(idx & 1023);
        int hcol = j >> 2, g = j & 3;
        size_t src = (size_t)(g * Hdim + hcol) * Hdim + k;
        float wi = Wih[src];
        float wc = wi + Whh[src];
        size_t dst = ((size_t)((j >> 7) * NCH + (k >> 6))) * TILE_ELEMS + (size_t)(j & 127) * 64 + (k & 63);
        __half h0 = __float2half_rn(wi);
        g_B0h[dst] = h0;
        g_B0l[dst] = __float2half_rn(wi - __half2float(h0));
        __half hc_ = __float2half_rn(wc);
        g_Bch[dst] = hc_;
        g_Bcl[dst] = __float2half_rn(wc - __half2float(hc_));
    }
    if (idx < (size_t)Bdim * Hdim) {
        int r = (int)(idx >> 10), k = (int)(idx & 1023);
        size_t dst = ((size_t)((r >> 7) * NCH + (k >> 6))) * TILE_ELEMS + (size_t)(r & 127) * 64 + (k & 63);
        g_xA[dst] = __float2half_rn(x[idx]);
    }
    if (idx < G4) {
        int hcol = (int)idx >> 2, g = (int)idx & 3;
        g_bp[idx] = bih[g * Hdim + hcol] + bhh[g * Hdim + hcol];
    }
    if (idx < (size_t)Hdim * DO) {
        int k = (int)(idx >> 7), d = (int)(idx & (DO - 1));
        g_WoT[idx] = Wout[(size_t)d * Hdim + k];
    }
}

// ---------------- t = 0 step (streamed, R4 design) ---------------------------
#define STG_SZ 40960
#define OFF_A  0
#define OFF_BH 8192
#define OFF_BL 24576
#define NSTG   3
#define STEP_SMEM (NSTG * STG_SZ)

__global__ void __launch_bounds__(256, 1) lstm_step0_kernel() {
    extern __shared__ char smem[];
    const uint32_t sb = smem_u32(smem);
    const int tid = threadIdx.x;
    const int wid = tid >> 5, lane = tid & 31;
    const int nt = blockIdx.x, mt = blockIdx.y;
    const int rt = mt >> 1, rl0 = (mt & 1) * 64;

    const __half* Aa = g_xA + (size_t)rt * NCH * TILE_ELEMS;
    const __half* Bh = g_B0h + (size_t)nt * NCH * TILE_ELEMS;
    const __half* Bl = g_B0l + (size_t)nt * NCH * TILE_ELEMS;

    const int ldrow = tid >> 3;
    const int ldcol = (tid & 7) * 16;

    auto issue = [&](int c) {
        if (c < NCH) {
            uint32_t stg = sb + (c % NSTG) * STG_SZ;
            const char* pa  = (const char*)(Aa + ((size_t)c * 128 + rl0) * 64);
            const char* pbh = (const char*)(Bh + (size_t)c * 128 * 64);
            const char* pbl = (const char*)(Bl + (size_t)c * 128 * 64);
            #pragma unroll
            for (int p = 0; p < 2; p++) {
                int r = ldrow + p * 32;
                uint32_t sw = r * 128 + (ldcol ^ ((r & 7) << 4));
                cpasync16(stg + OFF_A + sw, pa + r * 128 + ldcol);
            }
            #pragma unroll
            for (int p = 0; p < 4; p++) {
                int r = ldrow + p * 32;
                uint32_t sw = r * 128 + (ldcol ^ ((r & 7) << 4));
                cpasync16(stg + OFF_BH + sw, pbh + r * 128 + ldcol);
                cpasync16(stg + OFF_BL + sw, pbl + r * 128 + ldcol);
            }
        }
        cp_commit();
    };

    const int wr = wid >> 2, wc = wid & 3;
    const int mrow0 = wr * 32, n0 = wc * 32;

    float acc[2][4][4];
    #pragma unroll
    for (int mf = 0; mf < 2; mf++)
        #pragma unroll
        for (int nf = 0; nf < 4; nf++)
            #pragma unroll
            for (int q = 0; q < 4; q++) acc[mf][nf][q] = 0.0f;

    issue(0); issue(1);
    for (int c = 0; c < NCH; c++) {
        asm volatile("cp.async.wait_group 1;" ::: "memory");
        __syncthreads();
        uint32_t stg = sb + (c % NSTG) * STG_SZ;

        uint32_t fa[2][2][4], fbh[2][2][4], fbl[2][2][4];
        #pragma unroll
        for (int mf = 0; mf < 2; mf++)
            ldm_x4(fa[0][mf], tile_addr(stg + OFF_A, mrow0 + mf * 16, 0, lane));
        #pragma unroll
        for (int hf = 0; hf < 2; hf++) {
            ldm_x4(fbh[0][hf], tile_addr(stg + OFF_BH, n0 + hf * 16, 0, lane));
            ldm_x4(fbl[0][hf], tile_addr(stg + OFF_BL, n0 + hf * 16, 0, lane));
        }
        #pragma unroll
        for (int kst = 0; kst < 4; kst++) {
            const int cur = kst & 1, nxt = cur ^ 1;
            if (kst < 3) {
                const int k0 = (kst + 1) * 16;
                #pragma unroll
                for (int mf = 0; mf < 2; mf++)
                    ldm_x4(fa[nxt][mf], tile_addr(stg + OFF_A, mrow0 + mf * 16, k0, lane));
                #pragma unroll
                for (int hf = 0; hf < 2; hf++) {
                    ldm_x4(fbh[nxt][hf], tile_addr(stg + OFF_BH, n0 + hf * 16, k0, lane));
                    ldm_x4(fbl[nxt][hf], tile_addr(stg + OFF_BL, n0 + hf * 16, k0, lane));
                }
            }
            #pragma unroll
            for (int mf = 0; mf < 2; mf++)
                #pragma unroll
                for (int nf = 0; nf < 4; nf++) {
                    const int hf = nf >> 1, lo = nf & 1;
                    mma_f16(acc[mf][nf], fa[cur][mf], fbh[cur][hf][lo], fbh[cur][hf][lo + 2]);
                    mma_f16(acc[mf][nf], fa[cur][mf], fbl[cur][hf][lo], fbl[cur][hf][lo + 2]);
                }
        }
        issue(c + 2);
    }

    const int quad = lane >> 2, qp = lane & 3;
    const bool oddl = (lane & 1) != 0;
    const int mtb = mt * 64;

    #pragma unroll
    for (int mf = 0; mf < 2; mf++)
        #pragma unroll
        for (int nf = 0; nf < 4; nf++) {
            float* a = acc[mf][nf];
            int jb = nt * 128 + wc * 32 + nf * 8 + 2 * qp;
            float be = g_bp[jb], bo = g_bp[jb + 1];
            a[0] += be; a[1] += bo; a[2] += be; a[3] += bo;

            float p0 = __shfl_xor_sync(0xffffffffu, a[0], 1);
            float p1 = __shfl_xor_sync(0xffffffffu, a[1], 1);
            float p2 = __shfl_xor_sync(0xffffffffu, a[2], 1);
            float p3 = __shfl_xor_sync(0xffffffffu, a[3], 1);

            float vi = oddl ? p2 : a[0];
            float vf = oddl ? p3 : a[1];
            float vg = oddl ? a[2] : p0;
            float vo = oddl ? a[3] : p1;

            int row_g = mtb + wr * 32 + mf * 16 + quad + (oddl ? 8 : 0);
            int hc    = nt * 32 + wc * 8 + nf * 2 + (qp >> 1);

            float cn = sigf(vf) * 0.0f + sigf(vi) * tanhf_(vg);
            float hn = sigf(vo) * tanhf_(cn);
            g_c[(size_t)row_g * Hdim + hc] = cn;
            g_seq[((size_t)0 * Bdim + row_g) * Hdim + hc] = hn;

            int rt2 = row_g >> 7, rl = row_g & 127;
            size_t hb = ((((size_t)0 * 2 + rt2) * NCH + (hc >> 6)) * 128 + rl) * 64 + (hc & 63);
            g_hf[hb] = __float2half_rn(hn);
        }
}

// ---------------- persistent kernel: steps 1..127 ----------------------------
// 128 CTAs. CTA (nt, mt): rows [mt*128,+128), gate cols [nt*64,+64).
// SMEM: 3 streaming stages (A 16K + Blo 8K = 24K each) then resident W-hi 128K.
#define P_STG_SZ 24576
#define P_OFF_A  0
#define P_OFF_BL 16384
#define P_OFF_W  (3 * P_STG_SZ)
#define P_SMEM   (P_OFF_W + 131072)      // 204800

__global__ void __launch_bounds__(256, 1) lstm_persist_kernel() {
    extern __shared__ char smem[];
    const uint32_t sb = smem_u32(smem);
    const int tid = threadIdx.x;
    const int wid = tid >> 5, lane = tid & 31;
    const int nt = blockIdx.x >> 1, mt = blockIdx.x & 1;
    const int pt = nt >> 1, jr0 = (nt & 1) * 64;     // slice of packed 128-col tile

    const int ldrow = tid >> 3;
    const int ldcol = (tid & 7) * 16;
    const uint32_t sbW = sb + P_OFF_W;

    // ---- load resident hi weights: 16 chunks x (64 rows x 128B) = 128 KB ----
    {
        const char* wbase = (const char*)(g_Bch + (size_t)pt * NCH * TILE_ELEMS) + jr0 * 128;
        for (int c = 0; c < NCH; c++) {
            const char* src = wbase + (size_t)c * TILE_ELEMS * 2;
            #pragma unroll
            for (int p = 0; p < 2; p++) {
                int r = ldrow + p * 32;
                uint32_t sw = r * 128 + (ldcol ^ ((r & 7) << 4));
                cpasync16(sbW + c * 8192 + sw, src + r * 128 + ldcol);
            }
        }
        cp_commit();
        asm volatile("cp.async.wait_group 0;" ::: "memory");
        __syncthreads();
    }

    const int wr = wid >> 1, wc = wid & 1;           // 4x2 warps: 32 rows x 32 cols
    const int mrow0 = wr * 32, n0 = wc * 32;
    const int quad = lane >> 2, qp = lane & 3;
    const bool oddl = (lane & 1) != 0;

    // bias in registers (constant over steps)
    float bias0[4], bias1[4];
    #pragma unroll
    for (int nf = 0; nf < 4; nf++) {
        int jb = nt * 64 + wc * 32 + nf * 8 + 2 * qp;
        bias0[nf] = g_bp[jb];
        bias1[nf] = g_bp[jb + 1];
    }

    const char* BlBase = (const char*)(g_Bcl + (size_t)pt * NCH * TILE_ELEMS) + jr0 * 128;

    for (int t = 1; t < Tsteps; t++) {
        const __half* Aa = g_hf + ((size_t)(t - 1) * 2 + mt) * (NCH * TILE_ELEMS);

        auto issue = [&](int c) {
            if (c < NCH) {
                uint32_t stg = sb + (c % 3) * P_STG_SZ;
                const char* pa = (const char*)(Aa + (size_t)c * TILE_ELEMS);
                const char* pb = BlBase + (size_t)c * TILE_ELEMS * 2;
                #pragma unroll
                for (int p = 0; p < 4; p++) {
                    int r = ldrow + p * 32;
                    uint32_t sw = r * 128 + (ldcol ^ ((r & 7) << 4));
                    cpasync16(stg + P_OFF_A + sw, pa + r * 128 + ldcol);
                }
                #pragma unroll
                for (int p = 0; p < 2; p++) {
                    int r = ldrow + p * 32;
                    uint32_t sw = r * 128 + (ldcol ^ ((r & 7) << 4));
                    cpasync16(stg + P_OFF_BL + sw, pb + r * 128 + ldcol);
                }
            }
            cp_commit();
        };

        float acc[2][4][4];
        #pragma unroll
        for (int mf = 0; mf < 2; mf++)
            #pragma unroll
            for (int nf = 0; nf < 4; nf++)
                #pragma unroll
                for (int q = 0; q < 4; q++) acc[mf][nf][q] = 0.0f;

        issue(0); issue(1);
        for (int c = 0; c < NCH; c++) {
            asm volatile("cp.async.wait_group 1;" ::: "memory");
            __syncthreads();
            uint32_t stg = sb + (c % 3) * P_STG_SZ;
            uint32_t wch = sbW + c * 8192;

            uint32_t fa[2][2][4], fbh[2][2][4], fbl[2][2][4];
            #pragma unroll
            for (int mf = 0; mf < 2; mf++)
                ldm_x4(fa[0][mf], tile_addr(stg + P_OFF_A, mrow0 + mf * 16, 0, lane));
            #pragma unroll
            for (int hf = 0; hf < 2; hf++) {
                ldm_x4(fbh[0][hf], tile_addr(wch, n0 + hf * 16, 0, lane));
                ldm_x4(fbl[0][hf], tile_addr(stg + P_OFF_BL, n0 + hf * 16, 0, lane));
            }
            #pragma unroll
            for (int kst = 0; kst < 4; kst++) {
                const int cur = kst & 1, nxt = cur ^ 1;
                if (kst < 3) {
                    const int k0 = (kst + 1) * 16;
                    #pragma unroll
                    for (int mf = 0; mf < 2; mf++)
                        ldm_x4(fa[nxt][mf], tile_addr(stg + P_OFF_A, mrow0 + mf * 16, k0, lane));
                    #pragma unroll
                    for (int hf = 0; hf < 2; hf++) {
                        ldm_x4(fbh[nxt][hf], tile_addr(wch, n0 + hf * 16, k0, lane));
                        ldm_x4(fbl[nxt][hf], tile_addr(stg + P_OFF_BL, n0 + hf * 16, k0, lane));
                    }
                }
                #pragma unroll
                for (int mf = 0; mf < 2; mf++)
                    #pragma unroll
                    for (int nf = 0; nf < 4; nf++) {
                        const int hf = nf >> 1, lo = nf & 1;
                        mma_f16(acc[mf][nf], fa[cur][mf], fbh[cur][hf][lo], fbh[cur][hf][lo + 2]);
                        mma_f16(acc[mf][nf], fa[cur][mf], fbl[cur][hf][lo], fbl[cur][hf][lo + 2]);
                    }
            }
            issue(c + 2);
        }

        // ---- LSTM cell epilogue ----
        #pragma unroll
        for (int mf = 0; mf < 2; mf++)
            #pragma unroll
            for (int nf = 0; nf < 4; nf++) {
                float* a = acc[mf][nf];
                a[0] += bias0[nf]; a[1] += bias1[nf];
                a[2] += bias0[nf]; a[3] += bias1[nf];

                float p0 = __shfl_xor_sync(0xffffffffu, a[0], 1);
                float p1 = __shfl_xor_sync(0xffffffffu, a[1], 1);
                float p2 = __shfl_xor_sync(0xffffffffu, a[2], 1);
                float p3 = __shfl_xor_sync(0xffffffffu, a[3], 1);

                float vi = oddl ? p2 : a[0];
                float vf = oddl ? p3 : a[1];
                float vg = oddl ? a[2] : p0;
                float vo = oddl ? a[3] : p1;

                int row_g = mt * 128 + wr * 32 + mf * 16 + quad + (oddl ? 8 : 0);
                int hc    = nt * 16 + wc * 8 + nf * 2 + (qp >> 1);

                size_t cidx = (size_t)row_g * Hdim + hc;
                float cold = g_c[cidx];
                float cn = sigf(vf) * cold + sigf(vi) * tanhf_(vg);
                float hn = sigf(vo) * tanhf_(cn);
                g_c[cidx] = cn;

                g_seq[((size_t)t * Bdim + row_g) * Hdim + hc] = hn;

                int rl = row_g & 127;
                size_t hb = ((((size_t)t * 2 + mt) * NCH + (hc >> 6)) * 128 + rl) * 64 + (hc & 63);
                g_hf[hb] = __float2half_rn(hn);
            }

        if (t < Tsteps - 1) grid_bar();
    }
}

// ---------------- final projection (fp32 FFMA2) ------------------------------
__global__ void __launch_bounds__(256, 1) proj_kernel(const float* __restrict__ bout,
                                                      float* __restrict__ out) {
    __shared__ float As[32][65];
    __shared__ __align__(16) float Bs[32][128];

    const int tid = threadIdx.x;
    const int tx = tid & 15, ty = tid >> 4;
    const int r0 = blockIdx.x * 64;

    const int aK4 = tid & 7, aRow = tid >> 3;
    const int bJ4 = tid & 31, bK  = tid >> 5;

    ull acc[4][4];
    #pragma unroll
    for (int i = 0; i < 4; i++)
        #pragma unroll
        for (int p = 0; p < 4; p++) acc[i][p] = 0ull;

    float4 aReg[2], bReg[4];
    #pragma unroll
    for (int p = 0; p < 2; p++)
        aReg[p] = *(const float4*)&g_seq[(size_t)(r0 + aRow + p * 32) * Hdim + aK4 * 4];
    #pragma unroll
    for (int p = 0; p < 4; p++)
        bReg[p] = *(const float4*)&g_WoT[(size_t)(bK + p * 8) * DO + bJ4 * 4];

    for (int k0 = 0; k0 < Hdim; k0 += 32) {
        #pragma unroll
        for (int p = 0; p < 2; p++) {
            int row = aRow + p * 32;
            As[aK4 * 4 + 0][row] = aReg[p].x;
            As[aK4 * 4 + 1][row] = aReg[p].y;
            As[aK4 * 4 + 2][row] = aReg[p].z;
            As[aK4 * 4 + 3][row] = aReg[p].w;
        }
        #pragma unroll
        for (int p = 0; p < 4; p++)
            *(float4*)&Bs[bK + p * 8][bJ4 * 4] = bReg[p];
        __syncthreads();

        int kn = k0 + 32;
        if (kn < Hdim) {
            #pragma unroll
            for (int p = 0; p < 2; p++)
                aReg[p] = *(const float4*)&g_seq[(size_t)(r0 + aRow + p * 32) * Hdim + kn + aK4 * 4];
            #pragma unroll
            for (int p = 0; p < 4; p++)
                bReg[p] = *(const float4*)&g_WoT[(size_t)(kn + bK + p * 8) * DO + bJ4 * 4];
        }

        #pragma unroll
        for (int kk = 0; kk < 32; kk++) {
            ulonglong2 b01 = *(const ulonglong2*)&Bs[kk][tx * 8];
            ulonglong2 b23 = *(const ulonglong2*)&Bs[kk][tx * 8 + 4];
            #pragma unroll
            for (int i = 0; i < 4; i++) {
                ull Ar = pack2(As[kk][ty * 4 + i]);
                fma2(acc[i][0], Ar, b01.x);
                fma2(acc[i][1], Ar, b01.y);
                fma2(acc[i][2], Ar, b23.x);
                fma2(acc[i][3], Ar, b23.y);
            }
        }
        __syncthreads();
    }

    float bias[8];
    #pragma unroll
    for (int c = 0; c < 8; c++) bias[c] = bout[tx * 8 + c];

    #pragma unroll
    for (int i = 0; i < 4; i++) {
        int m_ = r0 + ty * 4 + i;          // m = t*256 + b
        int tt = m_ >> 8, bb = m_ & 255;
        float* orow = out + ((size_t)bb * Tsteps + tt) * DO;
        #pragma unroll
        for (int p = 0; p < 4; p++) {
            float2 v;
            v.x = lo32(acc[i][p]) + bias[2 * p + 0];
            v.y = hi32(acc[i][p]) + bias[2 * p + 1];
            *(float2*)&orow[tx * 8 + 2 * p] = v;
        }
    }
}

// ---------------- launcher ---------------------------------------------------
extern "C" void kernel_launch(void* const* d_in, const int* in_sizes, int n_in,
                              void* d_out, int out_size) {
    const float* x    = (const float*)d_in[0];
    const float* Wih  = (const float*)d_in[1];
    const float* Whh  = (const float*)d_in[2];
    const float* bih  = (const float*)d_in[3];
    const float* bhh  = (const float*)d_in[4];
    const float* Wout = (const float*)d_in[5];
    const float* bout = (const float*)d_in[6];
    float* out = (float*)d_out;

    cudaFuncSetAttribute(lstm_step0_kernel, cudaFuncAttributeMaxDynamicSharedMemorySize, STEP_SMEM);
    cudaFuncSetAttribute(lstm_persist_kernel, cudaFuncAttributeMaxDynamicSharedMemorySize, P_SMEM);

    pack_kernel<<<(G4 * Hdim) / 256, 256>>>(Wih, Whh, bih, bhh, Wout, x);
    lstm_step0_kernel<<<dim3(32, 4), 256, STEP_SMEM>>>();
    lstm_persist_kernel<<<128, 256, P_SMEM>>>();
    proj_kernel<<<(Tsteps * Bdim) / 64, 256>>>(bout, out);
}

// round 6
// speedup vs baseline: 4.0330x; 1.5538x over previous
#include <cuda_runtime.h>
#include <cuda_fp16.h>
#include <cstdint>

#define Bdim   256
#define Hdim   1024
#define G4     4096
#define Tsteps 128
#define DO     128
#define NCH    16                 // K chunks of 64
#define TILE_ELEMS (128 * 64)     // (128-row x 64-k) half tile

// ---------------- device scratch ------------------------------------------
__device__ __half g_B0h[(size_t)G4 * Hdim], g_B0l[(size_t)G4 * Hdim]; // W_ih fp16 hi/lo
__device__ __half g_Bch[(size_t)G4 * Hdim], g_Bcl[(size_t)G4 * Hdim]; // (W_ih+W_hh) fp16 hi/lo
__device__ __half g_xA[(size_t)Bdim * Hdim];                          // x fp16, tiled
__device__ __half g_hf[(size_t)Tsteps * Bdim * Hdim];                 // h fp16, tiled [t][rt][c][rl][kin]
__device__ __half g_Wph[(size_t)DO * Hdim], g_Wpl[(size_t)DO * Hdim]; // W_out fp16 hi/lo, [c][d][kin]
__device__ float g_c[(size_t)Bdim * Hdim];                            // cell state [r][hc]
__device__ float g_bp[G4];                                            // bias, j = hcol*4+gate
__device__ unsigned g_cnt = 0, g_gen = 0;                             // grid barrier state

// ---------------- helpers ---------------------------------------------------
__device__ __forceinline__ uint32_t smem_u32(const void* p) {
    uint32_t a;
    asm("{ .reg .u64 t; cvta.to.shared.u64 t, %1; cvt.u32.u64 %0, t; }" : "=r"(a) : "l"(p));
    return a;
}
__device__ __forceinline__ float sigf(float v)   { return 1.0f / (1.0f + __expf(-v)); }
__device__ __forceinline__ float tanhf_(float v) { return 2.0f / (1.0f + __expf(-2.0f * v)) - 1.0f; }

__device__ __forceinline__ void cpasync16(uint32_t dst, const void* src) {
    asm volatile("cp.async.cg.shared.global [%0], [%1], 16;" :: "r"(dst), "l"(src) : "memory");
}
__device__ __forceinline__ void cp_commit() { asm volatile("cp.async.commit_group;" ::: "memory"); }

__device__ __forceinline__ void ldm_x4(uint32_t* r, uint32_t addr) {
    asm volatile("ldmatrix.sync.aligned.m8n8.x4.shared.b16 {%0,%1,%2,%3}, [%4];"
                 : "=r"(r[0]), "=r"(r[1]), "=r"(r[2]), "=r"(r[3]) : "r"(addr));
}
__device__ __forceinline__ void mma_f16(float* d, const uint32_t* a, uint32_t b0, uint32_t b1) {
    asm volatile(
        "mma.sync.aligned.m16n8k16.row.col.f32.f16.f16.f32 "
        "{%0,%1,%2,%3}, {%4,%5,%6,%7}, {%8,%9}, {%0,%1,%2,%3};"
        : "+f"(d[0]), "+f"(d[1]), "+f"(d[2]), "+f"(d[3])
        : "r"(a[0]), "r"(a[1]), "r"(a[2]), "r"(a[3]), "r"(b0), "r"(b1));
}
__device__ __forceinline__ uint32_t tile_addr(uint32_t base, int row0, int k0, int lane) {
    int g = lane >> 3;
    int r = row0 + (lane & 7) + ((g & 1) << 3);
    int kE = k0 + ((g >> 1) << 3);
    return base + r * 128 + ((kE * 2) ^ ((r & 7) << 4));
}

// software grid barrier (128 co-resident CTAs)
__device__ __forceinline__ void grid_bar() {
    __syncthreads();
    if (threadIdx.x == 0) {
        __threadfence();
        unsigned gen = atomicAdd(&g_gen, 0u);
        if (atomicAdd(&g_cnt, 1u) == 127u) {
            atomicExch(&g_cnt, 0u);
            __threadfence();
            atomicAdd(&g_gen, 1u);
        } else {
            while (atomicAdd(&g_gen, 0u) == gen) __nanosleep(64);
        }
    }
    __syncthreads();
}

// ---------------- pack kernel ----------------------------------------------
__global__ void pack_kernel(const float* __restrict__ Wih, const float* __restrict__ Whh,
                            const float* __restrict__ bih, const float* __restrict__ bhh,
                            const float* __restrict__ Wout, const float* __restrict__ x) {
    size_t idx = (size_t)blockIdx.x * 256 + threadIdx.x;
    {
        int j = (int)(idx >> 10), k = (int)(idx & 1023);
        int hcol = j >> 2, g = j & 3;
        size_t src = (size_t)(g * Hdim + hcol) * Hdim + k;
        float wi = Wih[src];
        float wc = wi + Whh[src];
        size_t dst = ((size_t)((j >> 7) * NCH + (k >> 6))) * TILE_ELEMS + (size_t)(j & 127) * 64 + (k & 63);
        __half h0 = __float2half_rn(wi);
        g_B0h[dst] = h0;
        g_B0l[dst] = __float2half_rn(wi - __half2float(h0));
        __half hc_ = __float2half_rn(wc);
        g_Bch[dst] = hc_;
        g_Bcl[dst] = __float2half_rn(wc - __half2float(hc_));
    }
    if (idx < (size_t)Bdim * Hdim) {
        int r = (int)(idx >> 10), k = (int)(idx & 1023);
        size_t dst = ((size_t)((r >> 7) * NCH + (k >> 6))) * TILE_ELEMS + (size_t)(r & 127) * 64 + (k & 63);
        g_xA[dst] = __float2half_rn(x[idx]);
    }
    if (idx < G4) {
        int hcol = (int)idx >> 2, g = (int)idx & 3;
        g_bp[idx] = bih[g * Hdim + hcol] + bhh[g * Hdim + hcol];
    }
    if (idx < (size_t)Hdim * DO) {
        int k = (int)(idx >> 7), d = (int)(idx & (DO - 1));
        float v = Wout[(size_t)d * Hdim + k];
        size_t dst = (size_t)(k >> 6) * TILE_ELEMS + (size_t)d * 64 + (k & 63);
        __half h0 = __float2half_rn(v);
        g_Wph[dst] = h0;
        g_Wpl[dst] = __float2half_rn(v - __half2float(h0));
    }
}

// ---------------- t = 0 step (streamed, 256 thr) -----------------------------
#define STG_SZ 40960
#define OFF_A  0
#define OFF_BH 8192
#define OFF_BL 24576
#define STEP_SMEM (3 * STG_SZ)

__global__ void __launch_bounds__(256, 1) lstm_step0_kernel() {
    extern __shared__ char smem[];
    const uint32_t sb = smem_u32(smem);
    const int tid = threadIdx.x;
    const int wid = tid >> 5, lane = tid & 31;
    const int nt = blockIdx.x, mt = blockIdx.y;
    const int rt = mt >> 1, rl0 = (mt & 1) * 64;

    const __half* Aa = g_xA + (size_t)rt * NCH * TILE_ELEMS;
    const __half* Bh = g_B0h + (size_t)nt * NCH * TILE_ELEMS;
    const __half* Bl = g_B0l + (size_t)nt * NCH * TILE_ELEMS;

    const int ldrow = tid >> 3;
    const int ldcol = (tid & 7) * 16;

    auto issue = [&](int c) {
        if (c < NCH) {
            uint32_t stg = sb + (c % 3) * STG_SZ;
            const char* pa  = (const char*)(Aa + ((size_t)c * 128 + rl0) * 64);
            const char* pbh = (const char*)(Bh + (size_t)c * 128 * 64);
            const char* pbl = (const char*)(Bl + (size_t)c * 128 * 64);
            #pragma unroll
            for (int p = 0; p < 2; p++) {
                int r = ldrow + p * 32;
                uint32_t sw = r * 128 + (ldcol ^ ((r & 7) << 4));
                cpasync16(stg + OFF_A + sw, pa + r * 128 + ldcol);
            }
            #pragma unroll
            for (int p = 0; p < 4; p++) {
                int r = ldrow + p * 32;
                uint32_t sw = r * 128 + (ldcol ^ ((r & 7) << 4));
                cpasync16(stg + OFF_BH + sw, pbh + r * 128 + ldcol);
                cpasync16(stg + OFF_BL + sw, pbl + r * 128 + ldcol);
            }
        }
        cp_commit();
    };

    const int wr = wid >> 2, wc = wid & 3;
    const int mrow0 = wr * 32, n0 = wc * 32;

    float acc[2][4][4];
    #pragma unroll
    for (int mf = 0; mf < 2; mf++)
        #pragma unroll
        for (int nf = 0; nf < 4; nf++)
            #pragma unroll
            for (int q = 0; q < 4; q++) acc[mf][nf][q] = 0.0f;

    issue(0); issue(1);
    for (int c = 0; c < NCH; c++) {
        asm volatile("cp.async.wait_group 1;" ::: "memory");
        __syncthreads();
        uint32_t stg = sb + (c % 3) * STG_SZ;

        uint32_t fa[2][2][4], fbh[2][2][4], fbl[2][2][4];
        #pragma unroll
        for (int mf = 0; mf < 2; mf++)
            ldm_x4(fa[0][mf], tile_addr(stg + OFF_A, mrow0 + mf * 16, 0, lane));
        #pragma unroll
        for (int hf = 0; hf < 2; hf++) {
            ldm_x4(fbh[0][hf], tile_addr(stg + OFF_BH, n0 + hf * 16, 0, lane));
            ldm_x4(fbl[0][hf], tile_addr(stg + OFF_BL, n0 + hf * 16, 0, lane));
        }
        #pragma unroll
        for (int kst = 0; kst < 4; kst++) {
            const int cur = kst & 1, nxt = cur ^ 1;
            if (kst < 3) {
                const int k0 = (kst + 1) * 16;
                #pragma unroll
                for (int mf = 0; mf < 2; mf++)
                    ldm_x4(fa[nxt][mf], tile_addr(stg + OFF_A, mrow0 + mf * 16, k0, lane));
                #pragma unroll
                for (int hf = 0; hf < 2; hf++) {
                    ldm_x4(fbh[nxt][hf], tile_addr(stg + OFF_BH, n0 + hf * 16, k0, lane));
                    ldm_x4(fbl[nxt][hf], tile_addr(stg + OFF_BL, n0 + hf * 16, k0, lane));
                }
            }
            #pragma unroll
            for (int mf = 0; mf < 2; mf++)
                #pragma unroll
                for (int nf = 0; nf < 4; nf++) {
                    const int hf = nf >> 1, lo = nf & 1;
                    mma_f16(acc[mf][nf], fa[cur][mf], fbh[cur][hf][lo], fbh[cur][hf][lo + 2]);
                    mma_f16(acc[mf][nf], fa[cur][mf], fbl[cur][hf][lo], fbl[cur][hf][lo + 2]);
                }
        }
        issue(c + 2);
    }

    const int quad = lane >> 2, qp = lane & 3;
    const bool oddl = (lane & 1) != 0;
    const int mtb = mt * 64;

    #pragma unroll
    for (int mf = 0; mf < 2; mf++)
        #pragma unroll
        for (int nf = 0; nf < 4; nf++) {
            float* a = acc[mf][nf];
            int jb = nt * 128 + wc * 32 + nf * 8 + 2 * qp;
            float be = g_bp[jb], bo = g_bp[jb + 1];
            a[0] += be; a[1] += bo; a[2] += be; a[3] += bo;

            float p0 = __shfl_xor_sync(0xffffffffu, a[0], 1);
            float p1 = __shfl_xor_sync(0xffffffffu, a[1], 1);
            float p2 = __shfl_xor_sync(0xffffffffu, a[2], 1);
            float p3 = __shfl_xor_sync(0xffffffffu, a[3], 1);

            float vi = oddl ? p2 : a[0];
            float vf = oddl ? p3 : a[1];
            float vg = oddl ? a[2] : p0;
            float vo = oddl ? a[3] : p1;

            int row_g = mtb + wr * 32 + mf * 16 + quad + (oddl ? 8 : 0);
            int hc    = nt * 32 + wc * 8 + nf * 2 + (qp >> 1);

            float cn = sigf(vi) * tanhf_(vg);        // c0 = 0
            float hn = sigf(vo) * tanhf_(cn);
            g_c[(size_t)row_g * Hdim + hc] = cn;

            int rt2 = row_g >> 7, rl = row_g & 127;
            size_t hb = (((size_t)rt2 * NCH + (hc >> 6)) * 128 + rl) * 64 + (hc & 63);
            g_hf[hb] = __float2half_rn(hn);
        }
}

// ---------------- persistent kernel: steps 1..127, 512 threads ---------------
// 128 CTAs: nt = bid>>1 (64 gate cols), mt = bid&1 (128 rows).
// SMEM: 3 streaming stages (A 16K + Blo 8K) + resident W-hi 128K = 200K.
#define P_STG_SZ 24576
#define P_OFF_A  0
#define P_OFF_BL 16384
#define P_OFF_W  (3 * P_STG_SZ)
#define P_SMEM   (P_OFF_W + 131072)

__global__ void __launch_bounds__(512, 1) lstm_persist_kernel() {
    extern __shared__ char smem[];
    const uint32_t sb = smem_u32(smem);
    const int tid = threadIdx.x;
    const int wid = tid >> 5, lane = tid & 31;
    const int nt = blockIdx.x >> 1, mt = blockIdx.x & 1;
    const int pt = nt >> 1, jr0 = (nt & 1) * 64;

    const int ldrow = tid >> 3;            // 0..63
    const int ldcol = (tid & 7) * 16;
    const uint32_t sbW = sb + P_OFF_W;

    // resident hi weights: 16 chunks x (64 rows x 128B) = 128 KB
    {
        const char* wbase = (const char*)(g_Bch + (size_t)pt * NCH * TILE_ELEMS) + jr0 * 128;
        for (int c = 0; c < NCH; c++) {
            const char* src = wbase + (size_t)c * TILE_ELEMS * 2;
            uint32_t sw = ldrow * 128 + (ldcol ^ ((ldrow & 7) << 4));
            cpasync16(sbW + c * 8192 + sw, src + ldrow * 128 + ldcol);
        }
        cp_commit();
        asm volatile("cp.async.wait_group 0;" ::: "memory");
        __syncthreads();
    }

    const int wr = wid >> 2, wc = wid & 3;     // 4x4 warps: 32 rows x 16 cols
    const int mrow0 = wr * 32, n0 = wc * 16;
    const int quad = lane >> 2, qp = lane & 3;
    const bool oddl = (lane & 1) != 0;

    float bias0[2], bias1[2];
    #pragma unroll
    for (int nf = 0; nf < 2; nf++) {
        int jb = nt * 64 + wc * 16 + nf * 8 + 2 * qp;
        bias0[nf] = g_bp[jb];
        bias1[nf] = g_bp[jb + 1];
    }

    const char* BlBase = (const char*)(g_Bcl + (size_t)pt * NCH * TILE_ELEMS) + jr0 * 128;

    for (int t = 1; t < Tsteps; t++) {
        const __half* Aa = g_hf + ((size_t)(t - 1) * 2 + mt) * (NCH * TILE_ELEMS);

        auto issue = [&](int c) {
            if (c < NCH) {
                uint32_t stg = sb + (c % 3) * P_STG_SZ;
                const char* pa = (const char*)(Aa + (size_t)c * TILE_ELEMS);
                const char* pb = BlBase + (size_t)c * TILE_ELEMS * 2;
                #pragma unroll
                for (int p = 0; p < 2; p++) {
                    int r = ldrow + p * 64;
                    uint32_t sw = r * 128 + (ldcol ^ ((r & 7) << 4));
                    cpasync16(stg + P_OFF_A + sw, pa + r * 128 + ldcol);
                }
                {
                    uint32_t sw = ldrow * 128 + (ldcol ^ ((ldrow & 7) << 4));
                    cpasync16(stg + P_OFF_BL + sw, pb + ldrow * 128 + ldcol);
                }
            }
            cp_commit();
        };

        float acc[2][2][4];
        #pragma unroll
        for (int mf = 0; mf < 2; mf++)
            #pragma unroll
            for (int nf = 0; nf < 2; nf++)
                #pragma unroll
                for (int q = 0; q < 4; q++) acc[mf][nf][q] = 0.0f;

        issue(0); issue(1);
        for (int c = 0; c < NCH; c++) {
            asm volatile("cp.async.wait_group 1;" ::: "memory");
            __syncthreads();
            uint32_t stg = sb + (c % 3) * P_STG_SZ;
            uint32_t wch = sbW + c * 8192;

            uint32_t fa[2][2][4], fbh[2][4], fbl[2][4];
            #pragma unroll
            for (int mf = 0; mf < 2; mf++)
                ldm_x4(fa[0][mf], tile_addr(stg + P_OFF_A, mrow0 + mf * 16, 0, lane));
            ldm_x4(fbh[0], tile_addr(wch, n0, 0, lane));
            ldm_x4(fbl[0], tile_addr(stg + P_OFF_BL, n0, 0, lane));

            #pragma unroll
            for (int kst = 0; kst < 4; kst++) {
                const int cur = kst & 1, nxt = cur ^ 1;
                if (kst < 3) {
                    const int k0 = (kst + 1) * 16;
                    #pragma unroll
                    for (int mf = 0; mf < 2; mf++)
                        ldm_x4(fa[nxt][mf], tile_addr(stg + P_OFF_A, mrow0 + mf * 16, k0, lane));
                    ldm_x4(fbh[nxt], tile_addr(wch, n0, k0, lane));
                    ldm_x4(fbl[nxt], tile_addr(stg + P_OFF_BL, n0, k0, lane));
                }
                #pragma unroll
                for (int mf = 0; mf < 2; mf++)
                    #pragma unroll
                    for (int nf = 0; nf < 2; nf++) {
                        mma_f16(acc[mf][nf], fa[cur][mf], fbh[cur][nf], fbh[cur][nf + 2]);
                        mma_f16(acc[mf][nf], fa[cur][mf], fbl[cur][nf], fbl[cur][nf + 2]);
                    }
            }
            issue(c + 2);
        }

        // ---- LSTM cell epilogue ----
        #pragma unroll
        for (int mf = 0; mf < 2; mf++)
            #pragma unroll
            for (int nf = 0; nf < 2; nf++) {
                float* a = acc[mf][nf];
                a[0] += bias0[nf]; a[1] += bias1[nf];
                a[2] += bias0[nf]; a[3] += bias1[nf];

                float p0 = __shfl_xor_sync(0xffffffffu, a[0], 1);
                float p1 = __shfl_xor_sync(0xffffffffu, a[1], 1);
                float p2 = __shfl_xor_sync(0xffffffffu, a[2], 1);
                float p3 = __shfl_xor_sync(0xffffffffu, a[3], 1);

                float vi = oddl ? p2 : a[0];
                float vf = oddl ? p3 : a[1];
                float vg = oddl ? a[2] : p0;
                float vo = oddl ? a[3] : p1;

                int row_g = mt * 128 + wr * 32 + mf * 16 + quad + (oddl ? 8 : 0);
                int hc    = nt * 16 + wc * 4 + nf * 2 + (qp >> 1);

                size_t cidx = (size_t)row_g * Hdim + hc;
                float cold = g_c[cidx];
                float cn = sigf(vf) * cold + sigf(vi) * tanhf_(vg);
                float hn = sigf(vo) * tanhf_(cn);
                g_c[cidx] = cn;

                int rl = row_g & 127;
                size_t hb = ((((size_t)t * 2 + mt) * NCH + (hc >> 6)) * 128 + rl) * 64 + (hc & 63);
                g_hf[hb] = __float2half_rn(hn);
            }

        if (t < Tsteps - 1) grid_bar();
    }
}

// ---------------- projection (fp16 HMMA, 2-pass) -----------------------------
// grid 256: tb = t*2+rt. CTA = 128 rows x 128 out-cols, K=1024.
#define PJ_STG 49152
#define PJ_A   0
#define PJ_BH  16384
#define PJ_BL  32768
#define PJ_SMEM (3 * PJ_STG)

__global__ void __launch_bounds__(512, 1) proj_kernel(const float* __restrict__ bout,
                                                      float* __restrict__ out) {
    extern __shared__ char smem[];
    const uint32_t sb = smem_u32(smem);
    const int tid = threadIdx.x;
    const int wid = tid >> 5, lane = tid & 31;
    const int t = blockIdx.x >> 1, rt = blockIdx.x & 1;

    const __half* Aa = g_hf + ((size_t)t * 2 + rt) * (NCH * TILE_ELEMS);

    const int ldrow = tid >> 3;            // 0..63
    const int ldcol = (tid & 7) * 16;

    auto issue = [&](int c) {
        if (c < NCH) {
            uint32_t stg = sb + (c % 3) * PJ_STG;
            const char* pa  = (const char*)(Aa + (size_t)c * TILE_ELEMS);
            const char* pbh = (const char*)(g_Wph + (size_t)c * TILE_ELEMS);
            const char* pbl = (const char*)(g_Wpl + (size_t)c * TILE_ELEMS);
            #pragma unroll
            for (int p = 0; p < 2; p++) {
                int r = ldrow + p * 64;
                uint32_t sw = r * 128 + (ldcol ^ ((r & 7) << 4));
                cpasync16(stg + PJ_A + sw, pa + r * 128 + ldcol);
                cpasync16(stg + PJ_BH + sw, pbh + r * 128 + ldcol);
                cpasync16(stg + PJ_BL + sw, pbl + r * 128 + ldcol);
            }
        }
        cp_commit();
    };

    const int wr = wid >> 2, wc = wid & 3;     // 4x4: warp 32 rows x 32 cols
    const int mrow0 = wr * 32, n0 = wc * 32;

    float acc[2][4][4];
    #pragma unroll
    for (int mf = 0; mf < 2; mf++)
        #pragma unroll
        for (int nf = 0; nf < 4; nf++)
            #pragma unroll
            for (int q = 0; q < 4; q++) acc[mf][nf][q] = 0.0f;

    issue(0); issue(1);
    for (int c = 0; c < NCH; c++) {
        asm volatile("cp.async.wait_group 1;" ::: "memory");
        __syncthreads();
        uint32_t stg = sb + (c % 3) * PJ_STG;

        uint32_t fa[2][2][4], fbh[2][2][4], fbl[2][2][4];
        #pragma unroll
        for (int mf = 0; mf < 2; mf++)
            ldm_x4(fa[0][mf], tile_addr(stg + PJ_A, mrow0 + mf * 16, 0, lane));
        #pragma unroll
        for (int hf = 0; hf < 2; hf++) {
            ldm_x4(fbh[0][hf], tile_addr(stg + PJ_BH, n0 + hf * 16, 0, lane));
            ldm_x4(fbl[0][hf], tile_addr(stg + PJ_BL, n0 + hf * 16, 0, lane));
        }
        #pragma unroll
        for (int kst = 0; kst < 4; kst++) {
            const int cur = kst & 1, nxt = cur ^ 1;
            if (kst < 3) {
                const int k0 = (kst + 1) * 16;
                #pragma unroll
                for (int mf = 0; mf < 2; mf++)
                    ldm_x4(fa[nxt][mf], tile_addr(stg + PJ_A, mrow0 + mf * 16, k0, lane));
                #pragma unroll
                for (int hf = 0; hf < 2; hf++) {
                    ldm_x4(fbh[nxt][hf], tile_addr(stg + PJ_BH, n0 + hf * 16, k0, lane));
                    ldm_x4(fbl[nxt][hf], tile_addr(stg + PJ_BL, n0 + hf * 16, k0, lane));
                }
            }
            #pragma unroll
            for (int mf = 0; mf < 2; mf++)
                #pragma unroll
                for (int nf = 0; nf < 4; nf++) {
                    const int hf = nf >> 1, lo = nf & 1;
                    mma_f16(acc[mf][nf], fa[cur][mf], fbh[cur][hf][lo], fbh[cur][hf][lo + 2]);
                    mma_f16(acc[mf][nf], fa[cur][mf], fbl[cur][hf][lo], fbl[cur][hf][lo + 2]);
                }
        }
        issue(c + 2);
    }

    const int quad = lane >> 2, qp = lane & 3;
    #pragma unroll
    for (int mf = 0; mf < 2; mf++)
        #pragma unroll
        for (int nf = 0; nf < 4; nf++) {
            float* a = acc[mf][nf];
            int col = wc * 32 + nf * 8 + 2 * qp;
            float be = bout[col], bo = bout[col + 1];
            int row0 = wr * 32 + mf * 16 + quad;
            int b0 = rt * 128 + row0;
            float2 v0 = make_float2(a[0] + be, a[1] + bo);
            float2 v1 = make_float2(a[2] + be, a[3] + bo);
            *(float2*)&out[((size_t)b0 * Tsteps + t) * DO + col] = v0;
            *(float2*)&out[((size_t)(b0 + 8) * Tsteps + t) * DO + col] = v1;
        }
}

// ---------------- launcher ---------------------------------------------------
extern "C" void kernel_launch(void* const* d_in, const int* in_sizes, int n_in,
                              void* d_out, int out_size) {
    const float* x    = (const float*)d_in[0];
    const float* Wih  = (const float*)d_in[1];
    const float* Whh  = (const float*)d_in[2];
    const float* bih  = (const float*)d_in[3];
    const float* bhh  = (const float*)d_in[4];
    const float* Wout = (const float*)d_in[5];
    const float* bout = (const float*)d_in[6];
    float* out = (float*)d_out;

    cudaFuncSetAttribute(lstm_step0_kernel, cudaFuncAttributeMaxDynamicSharedMemorySize, STEP_SMEM);
    cudaFuncSetAttribute(lstm_persist_kernel, cudaFuncAttributeMaxDynamicSharedMemorySize, P_SMEM);
    cudaFuncSetAttribute(proj_kernel, cudaFuncAttributeMaxDynamicSharedMemorySize, PJ_SMEM);

    pack_kernel<<<(G4 * Hdim) / 256, 256>>>(Wih, Whh, bih, bhh, Wout, x);
    lstm_step0_kernel<<<dim3(32, 4), 256, STEP_SMEM>>>();
    lstm_persist_kernel<<<128, 512, P_SMEM>>>();
    proj_kernel<<<256, 512, PJ_SMEM>>>(bout, out);
}

// round 7
// speedup vs baseline: 5.2613x; 1.3046x over previous
#include <cuda_runtime.h>
#include <cuda_fp16.h>
#include <cstdint>

#define Bdim   256
#define Hdim   1024
#define G4     4096
#define Tsteps 128
#define DO     128
#define NCH    16                 // K chunks of 64
#define TILE_ELEMS (128 * 64)     // (128-row x 64-k) half tile

// ---------------- device scratch ------------------------------------------
__device__ __half g_B0[(size_t)G4 * Hdim];      // W_ih fp16, tiled [nt][c][jl][kin]
__device__ __half g_Bc[(size_t)G4 * Hdim];      // (W_ih+W_hh) fp16, tiled
__device__ __half g_xA[(size_t)Bdim * Hdim];    // x fp16, tiled [rt][c][rl][kin]
__device__ __half g_hf[(size_t)Tsteps * Bdim * Hdim]; // h fp16, tiled [t][rt][c][rl][kin]
__device__ __half g_Wp[(size_t)DO * Hdim];      // W_out fp16, [c][d][kin]
__device__ float g_c[(size_t)Bdim * Hdim];      // cell state [r][hc]
__device__ float g_bp[G4];                      // bias, j = hcol*4+gate
__device__ unsigned g_cnt2[2] = {0, 0}, g_gen2[2] = {0, 0};  // per-mt barrier

// ---------------- helpers ---------------------------------------------------
__device__ __forceinline__ uint32_t smem_u32(const void* p) {
    uint32_t a;
    asm("{ .reg .u64 t; cvta.to.shared.u64 t, %1; cvt.u32.u64 %0, t; }" : "=r"(a) : "l"(p));
    return a;
}
__device__ __forceinline__ float sigf(float v)   { return 1.0f / (1.0f + __expf(-v)); }
__device__ __forceinline__ float tanhf_(float v) { return 2.0f / (1.0f + __expf(-2.0f * v)) - 1.0f; }

__device__ __forceinline__ void cpasync16(uint32_t dst, const void* src) {
    asm volatile("cp.async.cg.shared.global [%0], [%1], 16;" :: "r"(dst), "l"(src) : "memory");
}
__device__ __forceinline__ void cp_commit() { asm volatile("cp.async.commit_group;" ::: "memory"); }

__device__ __forceinline__ void ldm_x4(uint32_t* r, uint32_t addr) {
    asm volatile("ldmatrix.sync.aligned.m8n8.x4.shared.b16 {%0,%1,%2,%3}, [%4];"
                 : "=r"(r[0]), "=r"(r[1]), "=r"(r[2]), "=r"(r[3]) : "r"(addr));
}
__device__ __forceinline__ void mma_f16(float* d, const uint32_t* a, uint32_t b0, uint32_t b1) {
    asm volatile(
        "mma.sync.aligned.m16n8k16.row.col.f32.f16.f16.f32 "
        "{%0,%1,%2,%3}, {%4,%5,%6,%7}, {%8,%9}, {%0,%1,%2,%3};"
        : "+f"(d[0]), "+f"(d[1]), "+f"(d[2]), "+f"(d[3])
        : "r"(a[0]), "r"(a[1]), "r"(a[2]), "r"(a[3]), "r"(b0), "r"(b1));
}
__device__ __forceinline__ uint32_t tile_addr(uint32_t base, int row0, int k0, int lane) {
    int g = lane >> 3;
    int r = row0 + (lane & 7) + ((g & 1) << 3);
    int kE = k0 + ((g >> 1) << 3);
    return base + r * 128 + ((kE * 2) ^ ((r & 7) << 4));
}

// per-mt software barrier (64 co-resident CTAs each)
__device__ __forceinline__ void grid_bar(int mt) {
    __syncthreads();
    if (threadIdx.x == 0) {
        __threadfence();
        unsigned gen = atomicAdd(&g_gen2[mt], 0u);
        if (atomicAdd(&g_cnt2[mt], 1u) == 63u) {
            atomicExch(&g_cnt2[mt], 0u);
            __threadfence();
            atomicAdd(&g_gen2[mt], 1u);
        } else {
            while (atomicAdd(&g_gen2[mt], 0u) == gen) __nanosleep(64);
        }
    }
    __syncthreads();
}

// ---------------- pack kernel ----------------------------------------------
__global__ void pack_kernel(const float* __restrict__ Wih, const float* __restrict__ Whh,
                            const float* __restrict__ bih, const float* __restrict__ bhh,
                            const float* __restrict__ Wout, const float* __restrict__ x) {
    size_t idx = (size_t)blockIdx.x * 256 + threadIdx.x;
    {
        int j = (int)(idx >> 10), k = (int)(idx & 1023);
        int hcol = j >> 2, g = j & 3;
        size_t src = (size_t)(g * Hdim + hcol) * Hdim + k;
        float wi = Wih[src];
        size_t dst = ((size_t)((j >> 7) * NCH + (k >> 6))) * TILE_ELEMS + (size_t)(j & 127) * 64 + (k & 63);
        g_B0[dst] = __float2half_rn(wi);
        g_Bc[dst] = __float2half_rn(wi + Whh[src]);
    }
    if (idx < (size_t)Bdim * Hdim) {
        int r = (int)(idx >> 10), k = (int)(idx & 1023);
        size_t dst = ((size_t)((r >> 7) * NCH + (k >> 6))) * TILE_ELEMS + (size_t)(r & 127) * 64 + (k & 63);
        g_xA[dst] = __float2half_rn(x[idx]);
    }
    if (idx < G4) {
        int hcol = (int)idx >> 2, g = (int)idx & 3;
        g_bp[idx] = bih[g * Hdim + hcol] + bhh[g * Hdim + hcol];
    }
    if (idx < (size_t)Hdim * DO) {
        int k = (int)(idx >> 7), d = (int)(idx & (DO - 1));
        size_t dst = (size_t)(k >> 6) * TILE_ELEMS + (size_t)d * 64 + (k & 63);
        g_Wp[dst] = __float2half_rn(Wout[(size_t)d * Hdim + k]);
    }
}

// ---------------- t = 0 step (streamed, 256 thr, single pass) ----------------
#define S0_STG 24576
#define S0_A   0
#define S0_B   8192
#define S0_SMEM (3 * S0_STG)

__global__ void __launch_bounds__(256, 1) lstm_step0_kernel() {
    extern __shared__ char smem[];
    const uint32_t sb = smem_u32(smem);
    const int tid = threadIdx.x;
    const int wid = tid >> 5, lane = tid & 31;
    const int nt = blockIdx.x, mt = blockIdx.y;
    const int rt = mt >> 1, rl0 = (mt & 1) * 64;

    const __half* Aa = g_xA + (size_t)rt * NCH * TILE_ELEMS;
    const __half* Bp = g_B0 + (size_t)nt * NCH * TILE_ELEMS;

    const int ldrow = tid >> 3;
    const int ldcol = (tid & 7) * 16;

    auto issue = [&](int c) {
        if (c < NCH) {
            uint32_t stg = sb + (c % 3) * S0_STG;
            const char* pa = (const char*)(Aa + ((size_t)c * 128 + rl0) * 64);
            const char* pb = (const char*)(Bp + (size_t)c * 128 * 64);
            #pragma unroll
            for (int p = 0; p < 2; p++) {
                int r = ldrow + p * 32;
                uint32_t sw = r * 128 + (ldcol ^ ((r & 7) << 4));
                cpasync16(stg + S0_A + sw, pa + r * 128 + ldcol);
            }
            #pragma unroll
            for (int p = 0; p < 4; p++) {
                int r = ldrow + p * 32;
                uint32_t sw = r * 128 + (ldcol ^ ((r & 7) << 4));
                cpasync16(stg + S0_B + sw, pb + r * 128 + ldcol);
            }
        }
        cp_commit();
    };

    const int wr = wid >> 2, wc = wid & 3;
    const int mrow0 = wr * 32, n0 = wc * 32;

    float acc[2][4][4];
    #pragma unroll
    for (int mf = 0; mf < 2; mf++)
        #pragma unroll
        for (int nf = 0; nf < 4; nf++)
            #pragma unroll
            for (int q = 0; q < 4; q++) acc[mf][nf][q] = 0.0f;

    issue(0); issue(1);
    for (int c = 0; c < NCH; c++) {
        asm volatile("cp.async.wait_group 1;" ::: "memory");
        __syncthreads();
        uint32_t stg = sb + (c % 3) * S0_STG;

        uint32_t fa[2][2][4], fb[2][2][4];
        #pragma unroll
        for (int mf = 0; mf < 2; mf++)
            ldm_x4(fa[0][mf], tile_addr(stg + S0_A, mrow0 + mf * 16, 0, lane));
        #pragma unroll
        for (int hf = 0; hf < 2; hf++)
            ldm_x4(fb[0][hf], tile_addr(stg + S0_B, n0 + hf * 16, 0, lane));
        #pragma unroll
        for (int kst = 0; kst < 4; kst++) {
            const int cur = kst & 1, nxt = cur ^ 1;
            if (kst < 3) {
                const int k0 = (kst + 1) * 16;
                #pragma unroll
                for (int mf = 0; mf < 2; mf++)
                    ldm_x4(fa[nxt][mf], tile_addr(stg + S0_A, mrow0 + mf * 16, k0, lane));
                #pragma unroll
                for (int hf = 0; hf < 2; hf++)
                    ldm_x4(fb[nxt][hf], tile_addr(stg + S0_B, n0 + hf * 16, k0, lane));
            }
            #pragma unroll
            for (int mf = 0; mf < 2; mf++)
                #pragma unroll
                for (int nf = 0; nf < 4; nf++) {
                    const int hf = nf >> 1, lo = nf & 1;
                    mma_f16(acc[mf][nf], fa[cur][mf], fb[cur][hf][lo], fb[cur][hf][lo + 2]);
                }
        }
        issue(c + 2);
    }

    const int quad = lane >> 2, qp = lane & 3;
    const bool oddl = (lane & 1) != 0;
    const int mtb = mt * 64;

    #pragma unroll
    for (int mf = 0; mf < 2; mf++)
        #pragma unroll
        for (int nf = 0; nf < 4; nf++) {
            float* a = acc[mf][nf];
            int jb = nt * 128 + wc * 32 + nf * 8 + 2 * qp;
            float be = g_bp[jb], bo = g_bp[jb + 1];
            a[0] += be; a[1] += bo; a[2] += be; a[3] += bo;

            float p0 = __shfl_xor_sync(0xffffffffu, a[0], 1);
            float p1 = __shfl_xor_sync(0xffffffffu, a[1], 1);
            float p2 = __shfl_xor_sync(0xffffffffu, a[2], 1);
            float p3 = __shfl_xor_sync(0xffffffffu, a[3], 1);

            float vi = oddl ? p2 : a[0];
            float vf = oddl ? p3 : a[1];
            float vg = oddl ? a[2] : p0;
            float vo = oddl ? a[3] : p1;

            int row_g = mtb + wr * 32 + mf * 16 + quad + (oddl ? 8 : 0);
            int hc    = nt * 32 + wc * 8 + nf * 2 + (qp >> 1);

            float cn = sigf(vi) * tanhf_(vg);        // c0 = 0
            float hn = sigf(vo) * tanhf_(cn);
            g_c[(size_t)row_g * Hdim + hc] = cn;

            int rt2 = row_g >> 7, rl = row_g & 127;
            size_t hb = (((size_t)rt2 * NCH + (hc >> 6)) * 128 + rl) * 64 + (hc & 63);
            g_hf[hb] = __float2half_rn(hn);
        }
}

// ---------------- persistent kernel: steps 1..127, 512 threads ---------------
// 128 CTAs: nt = bid>>1 (64 gate cols), mt = bid&1 (128 rows).
// SMEM: 4 streaming stages (A 16K) + resident W 128K = 192K.
#define P_STG_SZ 16384
#define P_OFF_W  (4 * P_STG_SZ)
#define P_SMEM   (P_OFF_W + 131072)

__global__ void __launch_bounds__(512, 1) lstm_persist_kernel() {
    extern __shared__ char smem[];
    const uint32_t sb = smem_u32(smem);
    const int tid = threadIdx.x;
    const int wid = tid >> 5, lane = tid & 31;
    const int nt = blockIdx.x >> 1, mt = blockIdx.x & 1;
    const int pt = nt >> 1, jr0 = (nt & 1) * 64;

    const int ldrow = tid >> 3;            // 0..63
    const int ldcol = (tid & 7) * 16;
    const uint32_t sbW = sb + P_OFF_W;

    // resident fp16 weights: 16 chunks x (64 rows x 128B) = 128 KB
    {
        const char* wbase = (const char*)(g_Bc + (size_t)pt * NCH * TILE_ELEMS) + jr0 * 128;
        for (int c = 0; c < NCH; c++) {
            const char* src = wbase + (size_t)c * TILE_ELEMS * 2;
            uint32_t sw = ldrow * 128 + (ldcol ^ ((ldrow & 7) << 4));
            cpasync16(sbW + c * 8192 + sw, src + ldrow * 128 + ldcol);
        }
        cp_commit();
        asm volatile("cp.async.wait_group 0;" ::: "memory");
        __syncthreads();
    }

    const int wr = wid >> 2, wc = wid & 3;     // 4x4 warps: 32 rows x 16 cols
    const int mrow0 = wr * 32, n0 = wc * 16;
    const int quad = lane >> 2, qp = lane & 3;
    const bool oddl = (lane & 1) != 0;

    float bias0[2], bias1[2];
    #pragma unroll
    for (int nf = 0; nf < 2; nf++) {
        int jb = nt * 64 + wc * 16 + nf * 8 + 2 * qp;
        bias0[nf] = g_bp[jb];
        bias1[nf] = g_bp[jb + 1];
    }

    for (int t = 1; t < Tsteps; t++) {
        const __half* Aa = g_hf + ((size_t)(t - 1) * 2 + mt) * (NCH * TILE_ELEMS);

        auto issue = [&](int c) {
            if (c < NCH) {
                uint32_t stg = sb + (c & 3) * P_STG_SZ;
                const char* pa = (const char*)(Aa + (size_t)c * TILE_ELEMS);
                #pragma unroll
                for (int p = 0; p < 2; p++) {
                    int r = ldrow + p * 64;
                    uint32_t sw = r * 128 + (ldcol ^ ((r & 7) << 4));
                    cpasync16(stg + sw, pa + r * 128 + ldcol);
                }
            }
            cp_commit();
        };

        float acc[2][2][4];
        #pragma unroll
        for (int mf = 0; mf < 2; mf++)
            #pragma unroll
            for (int nf = 0; nf < 2; nf++)
                #pragma unroll
                for (int q = 0; q < 4; q++) acc[mf][nf][q] = 0.0f;

        issue(0); issue(1); issue(2);
        for (int c = 0; c < NCH; c++) {
            asm volatile("cp.async.wait_group 2;" ::: "memory");
            __syncthreads();
            uint32_t stg = sb + (c & 3) * P_STG_SZ;
            uint32_t wch = sbW + c * 8192;

            uint32_t fa[2][2][4], fw[2][4];
            #pragma unroll
            for (int mf = 0; mf < 2; mf++)
                ldm_x4(fa[0][mf], tile_addr(stg, mrow0 + mf * 16, 0, lane));
            ldm_x4(fw[0], tile_addr(wch, n0, 0, lane));

            #pragma unroll
            for (int kst = 0; kst < 4; kst++) {
                const int cur = kst & 1, nxt = cur ^ 1;
                if (kst < 3) {
                    const int k0 = (kst + 1) * 16;
                    #pragma unroll
                    for (int mf = 0; mf < 2; mf++)
                        ldm_x4(fa[nxt][mf], tile_addr(stg, mrow0 + mf * 16, k0, lane));
                    ldm_x4(fw[nxt], tile_addr(wch, n0, k0, lane));
                }
                #pragma unroll
                for (int mf = 0; mf < 2; mf++)
                    #pragma unroll
                    for (int nf = 0; nf < 2; nf++)
                        mma_f16(acc[mf][nf], fa[cur][mf], fw[cur][nf], fw[cur][nf + 2]);
            }
            issue(c + 3);
        }

        // ---- LSTM cell epilogue ----
        #pragma unroll
        for (int mf = 0; mf < 2; mf++)
            #pragma unroll
            for (int nf = 0; nf < 2; nf++) {
                float* a = acc[mf][nf];
                a[0] += bias0[nf]; a[1] += bias1[nf];
                a[2] += bias0[nf]; a[3] += bias1[nf];

                float p0 = __shfl_xor_sync(0xffffffffu, a[0], 1);
                float p1 = __shfl_xor_sync(0xffffffffu, a[1], 1);
                float p2 = __shfl_xor_sync(0xffffffffu, a[2], 1);
                float p3 = __shfl_xor_sync(0xffffffffu, a[3], 1);

                float vi = oddl ? p2 : a[0];
                float vf = oddl ? p3 : a[1];
                float vg = oddl ? a[2] : p0;
                float vo = oddl ? a[3] : p1;

                int row_g = mt * 128 + wr * 32 + mf * 16 + quad + (oddl ? 8 : 0);
                int hc    = nt * 16 + wc * 4 + nf * 2 + (qp >> 1);

                size_t cidx = (size_t)row_g * Hdim + hc;
                float cold = g_c[cidx];
                float cn = sigf(vf) * cold + sigf(vi) * tanhf_(vg);
                float hn = sigf(vo) * tanhf_(cn);
                g_c[cidx] = cn;

                int rl = row_g & 127;
                size_t hb = ((((size_t)t * 2 + mt) * NCH + (hc >> 6)) * 128 + rl) * 64 + (hc & 63);
                g_hf[hb] = __float2half_rn(hn);
            }

        if (t < Tsteps - 1) grid_bar(mt);
    }
}

// ---------------- projection (fp16 HMMA, single pass) ------------------------
#define PJ_STG 32768
#define PJ_A   0
#define PJ_B   16384
#define PJ_SMEM (3 * PJ_STG)

__global__ void __launch_bounds__(512, 1) proj_kernel(const float* __restrict__ bout,
                                                      float* __restrict__ out) {
    extern __shared__ char smem[];
    const uint32_t sb = smem_u32(smem);
    const int tid = threadIdx.x;
    const int wid = tid >> 5, lane = tid & 31;
    const int t = blockIdx.x >> 1, rt = blockIdx.x & 1;

    const __half* Aa = g_hf + ((size_t)t * 2 + rt) * (NCH * TILE_ELEMS);

    const int ldrow = tid >> 3;            // 0..63
    const int ldcol = (tid & 7) * 16;

    auto issue = [&](int c) {
        if (c < NCH) {
            uint32_t stg = sb + (c % 3) * PJ_STG;
            const char* pa = (const char*)(Aa + (size_t)c * TILE_ELEMS);
            const char* pb = (const char*)(g_Wp + (size_t)c * TILE_ELEMS);
            #pragma unroll
            for (int p = 0; p < 2; p++) {
                int r = ldrow + p * 64;
                uint32_t sw = r * 128 + (ldcol ^ ((r & 7) << 4));
                cpasync16(stg + PJ_A + sw, pa + r * 128 + ldcol);
                cpasync16(stg + PJ_B + sw, pb + r * 128 + ldcol);
            }
        }
        cp_commit();
    };

    const int wr = wid >> 2, wc = wid & 3;     // 4x4: warp 32 rows x 32 cols
    const int mrow0 = wr * 32, n0 = wc * 32;

    float acc[2][4][4];
    #pragma unroll
    for (int mf = 0; mf < 2; mf++)
        #pragma unroll
        for (int nf = 0; nf < 4; nf++)
            #pragma unroll
            for (int q = 0; q < 4; q++) acc[mf][nf][q] = 0.0f;

    issue(0); issue(1);
    for (int c = 0; c < NCH; c++) {
        asm volatile("cp.async.wait_group 1;" ::: "memory");
        __syncthreads();
        uint32_t stg = sb + (c % 3) * PJ_STG;

        uint32_t fa[2][2][4], fb[2][2][4];
        #pragma unroll
        for (int mf = 0; mf < 2; mf++)
            ldm_x4(fa[0][mf], tile_addr(stg + PJ_A, mrow0 + mf * 16, 0, lane));
        #pragma unroll
        for (int hf = 0; hf < 2; hf++)
            ldm_x4(fb[0][hf], tile_addr(stg + PJ_B, n0 + hf * 16, 0, lane));
        #pragma unroll
        for (int kst = 0; kst < 4; kst++) {
            const int cur = kst & 1, nxt = cur ^ 1;
            if (kst < 3) {
                const int k0 = (kst + 1) * 16;
                #pragma unroll
                for (int mf = 0; mf < 2; mf++)
                    ldm_x4(fa[nxt][mf], tile_addr(stg + PJ_A, mrow0 + mf * 16, k0, lane));
                #pragma unroll
                for (int hf = 0; hf < 2; hf++)
                    ldm_x4(fb[nxt][hf], tile_addr(stg + PJ_B, n0 + hf * 16, k0, lane));
            }
            #pragma unroll
            for (int mf = 0; mf < 2; mf++)
                #pragma unroll
                for (int nf = 0; nf < 4; nf++) {
                    const int hf = nf >> 1, lo = nf & 1;
                    mma_f16(acc[mf][nf], fa[cur][mf], fb[cur][hf][lo], fb[cur][hf][lo + 2]);
                }
        }
        issue(c + 2);
    }

    const int quad = lane >> 2, qp = lane & 3;
    #pragma unroll
    for (int mf = 0; mf < 2; mf++)
        #pragma unroll
        for (int nf = 0; nf < 4; nf++) {
            float* a = acc[mf][nf];
            int col = wc * 32 + nf * 8 + 2 * qp;
            float be = bout[col], bo = bout[col + 1];
            int row0 = wr * 32 + mf * 16 + quad;
            int b0 = rt * 128 + row0;
            float2 v0 = make_float2(a[0] + be, a[1] + bo);
            float2 v1 = make_float2(a[2] + be, a[3] + bo);
            *(float2*)&out[((size_t)b0 * Tsteps + t) * DO + col] = v0;
            *(float2*)&out[((size_t)(b0 + 8) * Tsteps + t) * DO + col] = v1;
        }
}

// ---------------- launcher ---------------------------------------------------
extern "C" void kernel_launch(void* const* d_in, const int* in_sizes, int n_in,
                              void* d_out, int out_size) {
    const float* x    = (const float*)d_in[0];
    const float* Wih  = (const float*)d_in[1];
    const float* Whh  = (const float*)d_in[2];
    const float* bih  = (const float*)d_in[3];
    const float* bhh  = (const float*)d_in[4];
    const float* Wout = (const float*)d_in[5];
    const float* bout = (const float*)d_in[6];
    float* out = (float*)d_out;

    cudaFuncSetAttribute(lstm_step0_kernel, cudaFuncAttributeMaxDynamicSharedMemorySize, S0_SMEM);
    cudaFuncSetAttribute(lstm_persist_kernel, cudaFuncAttributeMaxDynamicSharedMemorySize, P_SMEM);
    cudaFuncSetAttribute(proj_kernel, cudaFuncAttributeMaxDynamicSharedMemorySize, PJ_SMEM);

    pack_kernel<<<(G4 * Hdim) / 256, 256>>>(Wih, Whh, bih, bhh, Wout, x);
    lstm_step0_kernel<<<dim3(32, 4), 256, S0_SMEM>>>();
    lstm_persist_kernel<<<128, 512, P_SMEM>>>();
    proj_kernel<<<256, 512, PJ_SMEM>>>(bout, out);
}

// round 8
// speedup vs baseline: 7.2794x; 1.3836x over previous
#include <cuda_runtime.h>
#include <cuda_fp16.h>
#include <cstdint>

#define Bdim   256
#define Hdim   1024
#define G4     4096
#define Tsteps 128
#define DO     128
#define NCH    8                     // K chunks of 128
#define AT_EL  16384                 // 128 rows x 128 kin halves (32 KB)
#define WT_EL  8192                  // 64 rows x 128 kin halves (16 KB)

// ---------------- device scratch ------------------------------------------
__device__ __half g_B0[(size_t)G4 * Hdim];      // W_ih fp16, [nt32][c8][jl128][kin128]
__device__ __half g_Bc[(size_t)G4 * Hdim];      // (W_ih+W_hh) fp16, [nt64][c8][jl64][kin128]
__device__ __half g_xA[(size_t)Bdim * Hdim];    // x fp16, [rt][c][rl][kin]
__device__ __half g_hf[(size_t)Tsteps * Bdim * Hdim]; // h fp16, [t][rt][c][rl][kin]
__device__ __half g_Wp[(size_t)DO * Hdim];      // W_out fp16, [c][d][kin]
__device__ float g_c[(size_t)Bdim * Hdim];      // cell state [r][hc] (step0 -> persist handoff)
__device__ float g_bp[G4];                      // bias, j = hcol*4+gate
__device__ unsigned g_flag[2][64];              // distributed barrier flags (zero-init)

// ---------------- helpers ---------------------------------------------------
__device__ __forceinline__ uint32_t smem_u32(const void* p) {
    uint32_t a;
    asm("{ .reg .u64 t; cvta.to.shared.u64 t, %1; cvt.u32.u64 %0, t; }" : "=r"(a) : "l"(p));
    return a;
}
__device__ __forceinline__ float sigf(float v)   { return 1.0f / (1.0f + __expf(-v)); }
__device__ __forceinline__ float tanhf_(float v) { return 2.0f / (1.0f + __expf(-2.0f * v)) - 1.0f; }

__device__ __forceinline__ void cpasync16(uint32_t dst, const void* src) {
    asm volatile("cp.async.cg.shared.global [%0], [%1], 16;" :: "r"(dst), "l"(src) : "memory");
}
__device__ __forceinline__ void cp_commit() { asm volatile("cp.async.commit_group;" ::: "memory"); }

__device__ __forceinline__ void ldm_x4(uint32_t* r, uint32_t addr) {
    asm volatile("ldmatrix.sync.aligned.m8n8.x4.shared.b16 {%0,%1,%2,%3}, [%4];"
                 : "=r"(r[0]), "=r"(r[1]), "=r"(r[2]), "=r"(r[3]) : "r"(addr));
}
__device__ __forceinline__ void mma_f16(float* d, const uint32_t* a, uint32_t b0, uint32_t b1) {
    asm volatile(
        "mma.sync.aligned.m16n8k16.row.col.f32.f16.f16.f32 "
        "{%0,%1,%2,%3}, {%4,%5,%6,%7}, {%8,%9}, {%0,%1,%2,%3};"
        : "+f"(d[0]), "+f"(d[1]), "+f"(d[2]), "+f"(d[3])
        : "r"(a[0]), "r"(a[1]), "r"(a[2]), "r"(a[3]), "r"(b0), "r"(b1));
}
// ldmatrix lane address into a 256B-row tile with per-8-row XOR swizzle
__device__ __forceinline__ uint32_t tile_addr2(uint32_t base, int row0, int k0, int lane) {
    int g = lane >> 3;
    int r = row0 + (lane & 7) + ((g & 1) << 3);
    int kE = k0 + ((g >> 1) << 3);
    return base + r * 256 + ((kE * 2) ^ ((r & 7) << 4));
}

// distributed-flag barrier: 64 CTAs per mt group, generation = t
__device__ __forceinline__ void grid_bar(int mt, int cta, unsigned t) {
    __syncthreads();
    if (threadIdx.x == 0) {
        __threadfence();                                  // publish h stores
        atomicExch(&g_flag[mt][cta], t);                  // own slot: no contention
    }
    if (threadIdx.x < 64) {
        while (atomicAdd(&g_flag[mt][threadIdx.x], 0u) < t) {}
        __threadfence();                                  // acquire before reading h
    }
    __syncthreads();
}

// ---------------- pack kernel ----------------------------------------------
__global__ void pack_kernel(const float* __restrict__ Wih, const float* __restrict__ Whh,
                            const float* __restrict__ bih, const float* __restrict__ bhh,
                            const float* __restrict__ Wout, const float* __restrict__ x) {
    size_t idx = (size_t)blockIdx.x * 256 + threadIdx.x;   // 0 .. G4*Hdim-1
    {
        int j = (int)(idx >> 10), k = (int)(idx & 1023);
        int hcol = j >> 2, g = j & 3;
        size_t src = (size_t)(g * Hdim + hcol) * Hdim + k;
        float wi = Wih[src];
        size_t d0 = ((size_t)((j >> 7) * NCH + (k >> 7))) * AT_EL + (size_t)(j & 127) * 128 + (k & 127);
        g_B0[d0] = __float2half_rn(wi);
        size_t dc = ((size_t)((j >> 6) * NCH + (k >> 7))) * WT_EL + (size_t)(j & 63) * 128 + (k & 127);
        g_Bc[dc] = __float2half_rn(wi + Whh[src]);
    }
    if (idx < (size_t)Bdim * Hdim) {
        int r = (int)(idx >> 10), k = (int)(idx & 1023);
        size_t dst = ((size_t)((r >> 7) * NCH + (k >> 7))) * AT_EL + (size_t)(r & 127) * 128 + (k & 127);
        g_xA[dst] = __float2half_rn(x[idx]);
    }
    if (idx < G4) {
        int hcol = (int)idx >> 2, g = (int)idx & 3;
        g_bp[idx] = bih[g * Hdim + hcol] + bhh[g * Hdim + hcol];
    }
    if (idx < (size_t)Hdim * DO) {
        int k = (int)(idx >> 7), d = (int)(idx & (DO - 1));
        size_t dst = (size_t)(k >> 7) * AT_EL + (size_t)d * 128 + (k & 127);
        g_Wp[dst] = __float2half_rn(Wout[(size_t)d * Hdim + k]);
    }
}

// ---------------- t = 0 step (streamed, 256 thr) -----------------------------
// grid (32 nt, 4 mt). CTA = 64 rows x 128 gate cols. stage: A 16K | B 32K.
#define S0_STG 49152
#define S0_A   0
#define S0_B   16384
#define S0_SMEM (3 * S0_STG)

__global__ void __launch_bounds__(256, 1) lstm_step0_kernel() {
    extern __shared__ char smem[];
    const uint32_t sb = smem_u32(smem);
    const int tid = threadIdx.x;
    const int wid = tid >> 5, lane = tid & 31;
    const int nt = blockIdx.x, mt = blockIdx.y;
    const int rt = mt >> 1, rl0 = (mt & 1) * 64;

    const char* Aa = (const char*)(g_xA + (size_t)rt * NCH * AT_EL) + rl0 * 256;
    const char* Bp = (const char*)(g_B0 + (size_t)nt * NCH * AT_EL);

    auto issue = [&](int c) {
        if (c < NCH) {
            uint32_t stg = sb + (c % 3) * S0_STG;
            const char* pa = Aa + (size_t)c * AT_EL * 2;
            const char* pb = Bp + (size_t)c * AT_EL * 2;
            {   // A: 64 rows x 256B
                int r = tid >> 2;
                #pragma unroll
                for (int p = 0; p < 4; p++) {
                    int kb = (tid & 3) * 16 + p * 64;
                    uint32_t sw = r * 256 + (kb ^ ((r & 7) << 4));
                    cpasync16(stg + S0_A + sw, pa + r * 256 + kb);
                }
            }
            {   // B: 128 rows x 256B
                int r = tid >> 1;
                #pragma unroll
                for (int p = 0; p < 8; p++) {
                    int kb = (tid & 1) * 16 + p * 32;
                    uint32_t sw = r * 256 + (kb ^ ((r & 7) << 4));
                    cpasync16(stg + S0_B + sw, pb + r * 256 + kb);
                }
            }
        }
        cp_commit();
    };

    const int wr = wid >> 2, wc = wid & 3;     // 2x4? no: 8 warps, warp = 32 rows x 32 cols
    const int mrow0 = wr * 32, n0 = wc * 32;

    float acc[2][4][4];
    #pragma unroll
    for (int mf = 0; mf < 2; mf++)
        #pragma unroll
        for (int nf = 0; nf < 4; nf++)
            #pragma unroll
            for (int q = 0; q < 4; q++) acc[mf][nf][q] = 0.0f;

    issue(0); issue(1);
    for (int c = 0; c < NCH; c++) {
        asm volatile("cp.async.wait_group 1;" ::: "memory");
        __syncthreads();
        uint32_t stg = sb + (c % 3) * S0_STG;

        uint32_t fa[2][2][4], fb[2][2][4];
        #pragma unroll
        for (int mf = 0; mf < 2; mf++)
            ldm_x4(fa[0][mf], tile_addr2(stg + S0_A, mrow0 + mf * 16, 0, lane));
        #pragma unroll
        for (int hf = 0; hf < 2; hf++)
            ldm_x4(fb[0][hf], tile_addr2(stg + S0_B, n0 + hf * 16, 0, lane));
        #pragma unroll
        for (int kst = 0; kst < 8; kst++) {
            const int cur = kst & 1, nxt = cur ^ 1;
            if (kst < 7) {
                const int k0 = (kst + 1) * 16;
                #pragma unroll
                for (int mf = 0; mf < 2; mf++)
                    ldm_x4(fa[nxt][mf], tile_addr2(stg + S0_A, mrow0 + mf * 16, k0, lane));
                #pragma unroll
                for (int hf = 0; hf < 2; hf++)
                    ldm_x4(fb[nxt][hf], tile_addr2(stg + S0_B, n0 + hf * 16, k0, lane));
            }
            #pragma unroll
            for (int mf = 0; mf < 2; mf++)
                #pragma unroll
                for (int nf = 0; nf < 4; nf++) {
                    const int hf = nf >> 1, lo = nf & 1;
                    mma_f16(acc[mf][nf], fa[cur][mf], fb[cur][hf][lo], fb[cur][hf][lo + 2]);
                }
        }
        issue(c + 2);
    }

    const int quad = lane >> 2, qp = lane & 3;
    const bool oddl = (lane & 1) != 0;
    const int mtb = mt * 64;

    #pragma unroll
    for (int mf = 0; mf < 2; mf++)
        #pragma unroll
        for (int nf = 0; nf < 4; nf++) {
            float* a = acc[mf][nf];
            int jb = nt * 128 + wc * 32 + nf * 8 + 2 * qp;
            float be = g_bp[jb], bo = g_bp[jb + 1];
            a[0] += be; a[1] += bo; a[2] += be; a[3] += bo;

            float p0 = __shfl_xor_sync(0xffffffffu, a[0], 1);
            float p1 = __shfl_xor_sync(0xffffffffu, a[1], 1);
            float p2 = __shfl_xor_sync(0xffffffffu, a[2], 1);
            float p3 = __shfl_xor_sync(0xffffffffu, a[3], 1);

            float vi = oddl ? p2 : a[0];
            float vf = oddl ? p3 : a[1];
            float vg = oddl ? a[2] : p0;
            float vo = oddl ? a[3] : p1;

            int row_g = mtb + wr * 32 + mf * 16 + quad + (oddl ? 8 : 0);
            int hc    = nt * 32 + wc * 8 + nf * 2 + (qp >> 1);

            float cn = sigf(vi) * tanhf_(vg);        // c0 = 0
            float hn = sigf(vo) * tanhf_(cn);
            g_c[(size_t)row_g * Hdim + hc] = cn;

            int rt2 = row_g >> 7, rl = row_g & 127;
            size_t hb = (((size_t)rt2 * NCH + (hc >> 7))) * AT_EL + (size_t)rl * 128 + (hc & 127);
            g_hf[hb] = __float2half_rn(hn);
        }
}

// ---------------- persistent kernel: steps 1..127, 512 threads ---------------
// 128 CTAs: nt = bid>>1 (64 gate cols), mt = bid&1 (128 rows).
// SMEM: 3 streaming A stages (32K) + resident W 128K = 224K.
#define P_STG_SZ 32768
#define P_OFF_W  (3 * P_STG_SZ)
#define P_SMEM   (P_OFF_W + 131072)      // 229376

__global__ void __launch_bounds__(512, 1) lstm_persist_kernel() {
    extern __shared__ char smem[];
    const uint32_t sb = smem_u32(smem);
    const int tid = threadIdx.x;
    const int wid = tid >> 5, lane = tid & 31;
    const int nt = blockIdx.x >> 1, mt = blockIdx.x & 1;
    const uint32_t sbW = sb + P_OFF_W;

    // resident fp16 weights: 8 chunks x (64 rows x 256B) = 128 KB
    {
        const char* wbase = (const char*)(g_Bc + (size_t)nt * NCH * WT_EL);
        for (int c = 0; c < NCH; c++) {
            const char* src = wbase + (size_t)c * WT_EL * 2;
            #pragma unroll
            for (int p = 0; p < 2; p++) {
                int r = (tid >> 4) + p * 32;
                int kb = (tid & 15) * 16;
                uint32_t sw = r * 256 + (kb ^ ((r & 7) << 4));
                cpasync16(sbW + c * 16384 + sw, src + r * 256 + kb);
            }
        }
        cp_commit();
        asm volatile("cp.async.wait_group 0;" ::: "memory");
        __syncthreads();
    }

    const int wr = wid >> 2, wc = wid & 3;     // 4x4 warps: 32 rows x 16 cols
    const int mrow0 = wr * 32, n0 = wc * 16;
    const int quad = lane >> 2, qp = lane & 3;
    const bool oddl = (lane & 1) != 0;

    // fixed output coordinates of this thread
    int rows[2], hcs[2];
    #pragma unroll
    for (int mf = 0; mf < 2; mf++)
        rows[mf] = mt * 128 + wr * 32 + mf * 16 + quad + (oddl ? 8 : 0);
    #pragma unroll
    for (int nf = 0; nf < 2; nf++)
        hcs[nf] = nt * 16 + wc * 4 + nf * 2 + (qp >> 1);

    // bias + cell state in registers
    float bias0[2], bias1[2], c_reg[2][2];
    #pragma unroll
    for (int nf = 0; nf < 2; nf++) {
        int jb = nt * 64 + wc * 16 + nf * 8 + 2 * qp;
        bias0[nf] = g_bp[jb];
        bias1[nf] = g_bp[jb + 1];
        #pragma unroll
        for (int mf = 0; mf < 2; mf++)
            c_reg[mf][nf] = g_c[(size_t)rows[mf] * Hdim + hcs[nf]];
    }

    for (int t = 1; t < Tsteps; t++) {
        const char* Aa = (const char*)(g_hf + ((size_t)(t - 1) * 2 + mt) * (NCH * AT_EL));

        auto issue = [&](int c) {
            if (c < NCH) {
                uint32_t stg = sb + (c % 3) * P_STG_SZ;
                const char* pa = Aa + (size_t)c * AT_EL * 2;
                int r = tid >> 2;
                #pragma unroll
                for (int p = 0; p < 4; p++) {
                    int kb = (tid & 3) * 16 + p * 64;
                    uint32_t sw = r * 256 + (kb ^ ((r & 7) << 4));
                    cpasync16(stg + sw, pa + r * 256 + kb);
                }
            }
            cp_commit();
        };

        float acc[2][2][4];
        #pragma unroll
        for (int mf = 0; mf < 2; mf++)
            #pragma unroll
            for (int nf = 0; nf < 2; nf++)
                #pragma unroll
                for (int q = 0; q < 4; q++) acc[mf][nf][q] = 0.0f;

        issue(0); issue(1);
        for (int c = 0; c < NCH; c++) {
            asm volatile("cp.async.wait_group 1;" ::: "memory");
            __syncthreads();
            uint32_t stg = sb + (c % 3) * P_STG_SZ;
            uint32_t wch = sbW + c * 16384;

            uint32_t fa[2][2][4], fw[2][4];
            #pragma unroll
            for (int mf = 0; mf < 2; mf++)
                ldm_x4(fa[0][mf], tile_addr2(stg, mrow0 + mf * 16, 0, lane));
            ldm_x4(fw[0], tile_addr2(wch, n0, 0, lane));

            #pragma unroll
            for (int kst = 0; kst < 8; kst++) {
                const int cur = kst & 1, nxt = cur ^ 1;
                if (kst < 7) {
                    const int k0 = (kst + 1) * 16;
                    #pragma unroll
                    for (int mf = 0; mf < 2; mf++)
                        ldm_x4(fa[nxt][mf], tile_addr2(stg, mrow0 + mf * 16, k0, lane));
                    ldm_x4(fw[nxt], tile_addr2(wch, n0, k0, lane));
                }
                #pragma unroll
                for (int mf = 0; mf < 2; mf++)
                    #pragma unroll
                    for (int nf = 0; nf < 2; nf++)
                        mma_f16(acc[mf][nf], fa[cur][mf], fw[cur][nf], fw[cur][nf + 2]);
            }
            issue(c + 2);
        }

        // ---- LSTM cell epilogue (c in registers) ----
        #pragma unroll
        for (int mf = 0; mf < 2; mf++)
            #pragma unroll
            for (int nf = 0; nf < 2; nf++) {
                float* a = acc[mf][nf];
                a[0] += bias0[nf]; a[1] += bias1[nf];
                a[2] += bias0[nf]; a[3] += bias1[nf];

                float p0 = __shfl_xor_sync(0xffffffffu, a[0], 1);
                float p1 = __shfl_xor_sync(0xffffffffu, a[1], 1);
                float p2 = __shfl_xor_sync(0xffffffffu, a[2], 1);
                float p3 = __shfl_xor_sync(0xffffffffu, a[3], 1);

                float vi = oddl ? p2 : a[0];
                float vf = oddl ? p3 : a[1];
                float vg = oddl ? a[2] : p0;
                float vo = oddl ? a[3] : p1;

                float cn = sigf(vf) * c_reg[mf][nf] + sigf(vi) * tanhf_(vg);
                float hn = sigf(vo) * tanhf_(cn);
                c_reg[mf][nf] = cn;

                int row_g = rows[mf], hc = hcs[nf];
                int rl = row_g & 127;
                size_t hb = (((size_t)t * 2 + mt) * NCH + (hc >> 7)) * AT_EL + (size_t)rl * 128 + (hc & 127);
                g_hf[hb] = __float2half_rn(hn);
            }

        if (t < Tsteps - 1) grid_bar(mt, nt, (unsigned)t);
    }
}

// ---------------- projection (fp16 HMMA) -------------------------------------
// grid 256: CTA = 128 rows x 128 out-cols, K=1024 in 8 chunks.
#define PJ_STG 65536
#define PJ_A   0
#define PJ_B   32768
#define PJ_SMEM (3 * PJ_STG)

__global__ void __launch_bounds__(512, 1) proj_kernel(const float* __restrict__ bout,
                                                      float* __restrict__ out) {
    extern __shared__ char smem[];
    const uint32_t sb = smem_u32(smem);
    const int tid = threadIdx.x;
    const int wid = tid >> 5, lane = tid & 31;
    const int t = blockIdx.x >> 1, rt = blockIdx.x & 1;

    const char* Aa = (const char*)(g_hf + ((size_t)t * 2 + rt) * (NCH * AT_EL));

    auto issue = [&](int c) {
        if (c < NCH) {
            uint32_t stg = sb + (c % 3) * PJ_STG;
            const char* pa = Aa + (size_t)c * AT_EL * 2;
            const char* pb = (const char*)(g_Wp + (size_t)c * AT_EL);
            int r = tid >> 2;
            #pragma unroll
            for (int p = 0; p < 4; p++) {
                int kb = (tid & 3) * 16 + p * 64;
                uint32_t sw = r * 256 + (kb ^ ((r & 7) << 4));
                cpasync16(stg + PJ_A + sw, pa + r * 256 + kb);
                cpasync16(stg + PJ_B + sw, pb + r * 256 + kb);
            }
        }
        cp_commit();
    };

    const int wr = wid >> 2, wc = wid & 3;     // warp = 32 rows x 32 cols
    const int mrow0 = wr * 32, n0 = wc * 32;

    float acc[2][4][4];
    #pragma unroll
    for (int mf = 0; mf < 2; mf++)
        #pragma unroll
        for (int nf = 0; nf < 4; nf++)
            #pragma unroll
            for (int q = 0; q < 4; q++) acc[mf][nf][q] = 0.0f;

    issue(0); issue(1);
    for (int c = 0; c < NCH; c++) {
        asm volatile("cp.async.wait_group 1;" ::: "memory");
        __syncthreads();
        uint32_t stg = sb + (c % 3) * PJ_STG;

        uint32_t fa[2][2][4], fb[2][2][4];
        #pragma unroll
        for (int mf = 0; mf < 2; mf++)
            ldm_x4(fa[0][mf], tile_addr2(stg + PJ_A, mrow0 + mf * 16, 0, lane));
        #pragma unroll
        for (int hf = 0; hf < 2; hf++)
            ldm_x4(fb[0][hf], tile_addr2(stg + PJ_B, n0 + hf * 16, 0, lane));
        #pragma unroll
        for (int kst = 0; kst < 8; kst++) {
            const int cur = kst & 1, nxt = cur ^ 1;
            if (kst < 7) {
                const int k0 = (kst + 1) * 16;
                #pragma unroll
                for (int mf = 0; mf < 2; mf++)
                    ldm_x4(fa[nxt][mf], tile_addr2(stg + PJ_A, mrow0 + mf * 16, k0, lane));
                #pragma unroll
                for (int hf = 0; hf < 2; hf++)
                    ldm_x4(fb[nxt][hf], tile_addr2(stg + PJ_B, n0 + hf * 16, k0, lane));
            }
            #pragma unroll
            for (int mf = 0; mf < 2; mf++)
                #pragma unroll
                for (int nf = 0; nf < 4; nf++) {
                    const int hf = nf >> 1, lo = nf & 1;
                    mma_f16(acc[mf][nf], fa[cur][mf], fb[cur][hf][lo], fb[cur][hf][lo + 2]);
                }
        }
        issue(c + 2);
    }

    const int quad = lane >> 2, qp = lane & 3;
    #pragma unroll
    for (int mf = 0; mf < 2; mf++)
        #pragma unroll
        for (int nf = 0; nf < 4; nf++) {
            float* a = acc[mf][nf];
            int col = wc * 32 + nf * 8 + 2 * qp;
            float be = bout[col], bo = bout[col + 1];
            int row0 = wr * 32 + mf * 16 + quad;
            int b0 = rt * 128 + row0;
            float2 v0 = make_float2(a[0] + be, a[1] + bo);
            float2 v1 = make_float2(a[2] + be, a[3] + bo);
            *(float2*)&out[((size_t)b0 * Tsteps + t) * DO + col] = v0;
            *(float2*)&out[((size_t)(b0 + 8) * Tsteps + t) * DO + col] = v1;
        }
}

// ---------------- launcher ---------------------------------------------------
extern "C" void kernel_launch(void* const* d_in, const int* in_sizes, int n_in,
                              void* d_out, int out_size) {
    const float* x    = (const float*)d_in[0];
    const float* Wih  = (const float*)d_in[1];
    const float* Whh  = (const float*)d_in[2];
    const float* bih  = (const float*)d_in[3];
    const float* bhh  = (const float*)d_in[4];
    const float* Wout = (const float*)d_in[5];
    const float* bout = (const float*)d_in[6];
    float* out = (float*)d_out;

    cudaFuncSetAttribute(lstm_step0_kernel, cudaFuncAttributeMaxDynamicSharedMemorySize, S0_SMEM);
    cudaFuncSetAttribute(lstm_persist_kernel, cudaFuncAttributeMaxDynamicSharedMemorySize, P_SMEM);
    cudaFuncSetAttribute(proj_kernel, cudaFuncAttributeMaxDynamicSharedMemorySize, PJ_SMEM);

    pack_kernel<<<(G4 * Hdim) / 256, 256>>>(Wih, Whh, bih, bhh, Wout, x);
    lstm_step0_kernel<<<dim3(32, 4), 256, S0_SMEM>>>();
    lstm_persist_kernel<<<128, 512, P_SMEM>>>();
    proj_kernel<<<256, 512, PJ_SMEM>>>(bout, out);
}